// round 9
// baseline (speedup 1.0000x reference)
#include <cuda_runtime.h>
#include <cuda_bf16.h>
#include <cstdint>

// ---------------- problem constants ----------------
#define BS     16384
#define MSEG   6
#define DM     512
#define NH     8
#define DIN    6144
#define NROWS  (BS*MSEG)            // 98304
#define QKV_ELEMS (NROWS*DM)        // 50331648
#define NLOGITS (BS*NH*36)
#define INV_TEMP 0.125f
#define LN_EPS 1e-6f
#define WPACK  9437184              // 512*6144*3

// ---------------- scratch ----------------
__device__ float g_Q[QKV_ELEMS];
__device__ float g_K[QKV_ELEMS];
__device__ float g_V[QKV_ELEMS];
__device__ float g_logits[NLOGITS];
__device__ unsigned g_min_bits;
__device__ __nv_bfloat16 g_Ah[(size_t)BS*DIN];
__device__ __nv_bfloat16 g_Al[(size_t)BS*DIN];
__device__ __nv_bfloat16 g_Wh[WPACK];
__device__ __nv_bfloat16 g_Wl[WPACK];
__device__ __nv_bfloat16 g_FWh[DM*DM];
__device__ __nv_bfloat16 g_FWl[DM*DM];
__device__ __nv_bfloat16 g_AOh[QKV_ELEMS];
__device__ __nv_bfloat16 g_AOl[QKV_ELEMS];

// combo c = s*3 + w  (w: 0=q, 1=k, 2=v)
__constant__ int c_cK[18]   = {2048,2048,2048,1024,1024,1024,512,512,512,
                               1536,1536,1536,768,768,768,256,256,256};
__constant__ int c_cOff[18] = {0,0,0,2048,2048,2048,3072,3072,3072,
                               3584,3584,3584,5120,5120,5120,5888,5888,5888};
__constant__ int c_cW[18]   = {0,1048576,2097152,3145728,3670016,4194304,
                               4718592,4980736,5242880,5505024,6291456,7077888,
                               7864320,8257536,8650752,9043968,9175040,9306112};

struct WPtrs { const float* w[18]; };

// ---------------- helpers ----------------
__device__ __forceinline__ uint32_t smem_u32(const void* p) {
    uint32_t a;
    asm("{ .reg .u64 t; cvta.to.shared.u64 t, %1; cvt.u32.u64 %0, t; }" : "=r"(a) : "l"(p));
    return a;
}
__device__ __forceinline__ void cpa16(uint32_t s, const void* g) {
    asm volatile("cp.async.cg.shared.global [%0], [%1], 16;" :: "r"(s), "l"(g));
}
__device__ __forceinline__ void cpa_commit() { asm volatile("cp.async.commit_group;" ::: "memory"); }
__device__ __forceinline__ void cpa_wait2()  { asm volatile("cp.async.wait_group 2;" ::: "memory"); }

__device__ __forceinline__ void mma16816(float* c, const uint32_t* a, const uint32_t* b) {
    asm volatile(
        "mma.sync.aligned.m16n8k16.row.col.f32.bf16.bf16.f32 "
        "{%0,%1,%2,%3}, {%4,%5,%6,%7}, {%8,%9}, {%0,%1,%2,%3};"
        : "+f"(c[0]), "+f"(c[1]), "+f"(c[2]), "+f"(c[3])
        : "r"(a[0]), "r"(a[1]), "r"(a[2]), "r"(a[3]), "r"(b[0]), "r"(b[1]));
}
__device__ __forceinline__ void ldm_x4(uint32_t* r, uint32_t addr) {
    asm volatile("ldmatrix.sync.aligned.m8n8.x4.shared.b16 {%0,%1,%2,%3}, [%4];"
        : "=r"(r[0]), "=r"(r[1]), "=r"(r[2]), "=r"(r[3]) : "r"(addr));
}

// ---------------- min encoding ----------------
__device__ __forceinline__ unsigned fenc(float f) {
    unsigned u = __float_as_uint(f);
    return (u & 0x80000000u) ? ~u : (u | 0x80000000u);
}
__device__ __forceinline__ float fdec(unsigned e) {
    unsigned u = (e & 0x80000000u) ? (e & 0x7fffffffu) : ~e;
    return __uint_as_float(u);
}

// ---------------- conversion kernels ----------------
__device__ __forceinline__ void split4(float4 x, __nv_bfloat16* h, __nv_bfloat16* l) {
    float v[4] = {x.x, x.y, x.z, x.w};
#pragma unroll
    for (int i = 0; i < 4; i++) {
        __nv_bfloat16 hi = __float2bfloat16_rn(v[i]);
        h[i] = hi;
        l[i] = __float2bfloat16_rn(v[i] - __bfloat162float(hi));
    }
}

__global__ void __launch_bounds__(256) conv_input_kernel(const float* __restrict__ inp) {
    size_t i = (size_t)blockIdx.x * 256 + threadIdx.x;   // float4 index
    if (i == 0) g_min_bits = 0xFFFFFFFFu;
    float4 x = ((const float4*)inp)[i];
    __nv_bfloat16 h[4], l[4];
    split4(x, h, l);
#pragma unroll
    for (int j = 0; j < 4; j++) { g_Ah[i*4+j] = h[j]; g_Al[i*4+j] = l[j]; }
}

__global__ void __launch_bounds__(256) conv_w_kernel(WPtrs P) {
    int c = blockIdx.y;
    int n4 = (512 * c_cK[c]) >> 2;
    int i = blockIdx.x * 256 + threadIdx.x;
    if (i >= n4) return;
    float4 x = ((const float4*)P.w[c])[i];
    __nv_bfloat16 h[4], l[4];
    split4(x, h, l);
    size_t base = (size_t)c_cW[c] + (size_t)i * 4;
#pragma unroll
    for (int j = 0; j < 4; j++) { g_Wh[base+j] = h[j]; g_Wl[base+j] = l[j]; }
}

__global__ void __launch_bounds__(256) conv_fcw_kernel(const float* __restrict__ fcw) {
    int i = blockIdx.x * 256 + threadIdx.x;   // 65536 float4s
    float4 x = ((const float4*)fcw)[i];
    __nv_bfloat16 h[4], l[4];
    split4(x, h, l);
#pragma unroll
    for (int j = 0; j < 4; j++) { g_FWh[i*4+j] = h[j]; g_FWl[i*4+j] = l[j]; }
}

// ---------------- mma.sync GEMM configuration ----------------
// CTA tile 128x128, BK=16 bf16, 4-stage pipeline, 2 CTAs/SM.
// smem stage: [Ah | Al | Bh | Bl], each 128 rows x 24 bf16 (pitch 48B, 32B data).
// ldmatrix conflict-free: chunk phase (3r + c) mod 8 is a permutation over r.
#define BUFB   6144               // bytes per buffer (128*48)
#define STAGE_BYTES (4*BUFB)      // 24576
#define NSTAGE 4
#define GEMM_SMEM (NSTAGE*STAGE_BYTES)   // 98304

// one stage: each thread does 4 cp.async (one per buffer); 1024 chunks total
__device__ __forceinline__ void load_stage_g(
    uint32_t sbase, int tid,
    const char* Ah, const char* Al, size_t strA,
    const char* Bh, const char* Bl, size_t strB, size_t kb)
{
    int r = tid >> 1, cc = tid & 1;
    uint32_t so = (uint32_t)(r * 48 + cc * 16);
    size_t ga = (size_t)r * strA + kb + cc * 16;
    size_t gb = (size_t)r * strB + kb + cc * 16;
    cpa16(sbase + so,            Ah + ga);
    cpa16(sbase + BUFB + so,     Al + ga);
    cpa16(sbase + 2*BUFB + so,   Bh + gb);
    cpa16(sbase + 3*BUFB + so,   Bl + gb);
    cpa_commit();
}

// per-lane ldmatrix offsets (bytes, relative to buffer base), pitch 48B
__device__ __forceinline__ void ldm_offsets(int wm, int wn, int lane,
                                            uint32_t& aoff, uint32_t& boff)
{
    int g = lane >> 3, r8 = lane & 7;
    int arow = wm * 32 + r8 + (g & 1) * 8;       // rows; (g>>1) selects k-half
    aoff = (uint32_t)(arow * 48 + (g >> 1) * 16);
    int brow = wn * 64 + r8 + (g >> 1) * 8;      // n rows; (g&1) selects k-half
    boff = (uint32_t)(brow * 48 + (g & 1) * 16);
}

// compute one BK=16 stage: 12 ldmatrix + 48 HMMA per warp
__device__ __forceinline__ void compute_stage(
    uint32_t sstage, uint32_t aoff, uint32_t boff, float acc[2][8][4])
{
    const uint32_t Ah_ = sstage,            Al_ = sstage + BUFB;
    const uint32_t Bh_ = sstage + 2*BUFB,   Bl_ = sstage + 3*BUFB;

    uint32_t ah[2][4], al[2][4];
#pragma unroll
    for (int mt = 0; mt < 2; mt++) {
        ldm_x4(ah[mt], Ah_ + aoff + mt * 768);      // 16 rows * 48B
        ldm_x4(al[mt], Al_ + aoff + mt * 768);
    }
#pragma unroll
    for (int p = 0; p < 4; p++) {                   // nt pairs
        uint32_t bh[4], bl[4];
        ldm_x4(bh, Bh_ + boff + p * 768);
        ldm_x4(bl, Bl_ + boff + p * 768);
#pragma unroll
        for (int mt = 0; mt < 2; mt++) {
            mma16816(acc[mt][2*p],   ah[mt], bh);
            mma16816(acc[mt][2*p+1], ah[mt], bh + 2);
            mma16816(acc[mt][2*p],   ah[mt], bl);
            mma16816(acc[mt][2*p+1], ah[mt], bl + 2);
            mma16816(acc[mt][2*p],   al[mt], bh);
            mma16816(acc[mt][2*p+1], al[mt], bh + 2);
        }
    }
}

// shared GEMM mainloop: 4-stage ring, one barrier per iteration
__device__ __forceinline__ void gemm_mainloop(
    uint32_t sb, int tid, int nc,
    const char* Ah, const char* Al, size_t strA,
    const char* Bh, const char* Bl, size_t strB,
    uint32_t aoff, uint32_t boff, float acc[2][8][4])
{
    load_stage_g(sb,                 tid, Ah, Al, strA, Bh, Bl, strB, 0);
    load_stage_g(sb + STAGE_BYTES,   tid, Ah, Al, strA, Bh, Bl, strB, 32);
    load_stage_g(sb + 2*STAGE_BYTES, tid, Ah, Al, strA, Bh, Bl, strB, 64);

    for (int i = 0; i < nc; i++) {
        cpa_wait2();                 // stage i landed (i+1, i+2 may be in flight)
        __syncthreads();             // all see stage i; stage (i+3)%4 free to overwrite
        if (i + 3 < nc)
            load_stage_g(sb + ((i+3) & 3) * STAGE_BYTES, tid,
                         Ah, Al, strA, Bh, Bl, strB, (size_t)(i+3) * 32);
        else
            cpa_commit();            // empty group keeps wait_group accounting exact
        compute_stage(sb + (i & 3) * STAGE_BYTES, aoff, boff, acc);
    }
    __syncthreads();
}

// ---------------- QKV GEMM ----------------
// grid (4 ntiles, 128 mtiles, 18 combos), 256 threads.
__global__ void __launch_bounds__(256, 2)
qkv_mma_kernel()
{
    extern __shared__ char smem[];
    const uint32_t sb = smem_u32(smem);
    const int tid = threadIdx.x, wid = tid >> 5, lane = tid & 31;
    const int wm = wid & 3, wn = wid >> 2;
    const int n0 = blockIdx.x * 128;
    const int m0 = blockIdx.y * 128;
    const int c  = blockIdx.z;
    const int Kdim = c_cK[c];
    const int seg  = c_cOff[c];
    const int s = c / 3, w = c % 3;
    const int nc = Kdim >> 4;

    const char* Ah = (const char*)(g_Ah + (size_t)m0 * DIN + seg);
    const char* Al = (const char*)(g_Al + (size_t)m0 * DIN + seg);
    const char* Bh = (const char*)(g_Wh + (size_t)c_cW[c] + (size_t)n0 * Kdim);
    const char* Bl = (const char*)(g_Wl + (size_t)c_cW[c] + (size_t)n0 * Kdim);
    const size_t strA = (size_t)DIN * 2, strB = (size_t)Kdim * 2;

    uint32_t aoff, boff;
    ldm_offsets(wm, wn, lane, aoff, boff);

    float acc[2][8][4];
#pragma unroll
    for (int i = 0; i < 2; i++)
#pragma unroll
        for (int j = 0; j < 8; j++)
#pragma unroll
            for (int k = 0; k < 4; k++) acc[i][j][k] = 0.0f;

    gemm_mainloop(sb, tid, nc, Ah, Al, strA, Bh, Bl, strB, aoff, boff, acc);

    // epilogue: acc -> smem (128 x 132 fp32) -> coalesced global
    float* tb = (float*)smem;
    {
        const int l4 = lane >> 2, lm = lane & 3;
#pragma unroll
        for (int mt = 0; mt < 2; mt++)
#pragma unroll
            for (int nt = 0; nt < 8; nt++) {
                int R = wm*32 + mt*16 + l4;
                int C = wn*64 + nt*8 + lm*2;
                tb[R*132 + C]       = acc[mt][nt][0];
                tb[R*132 + C + 1]   = acc[mt][nt][1];
                tb[(R+8)*132 + C]   = acc[mt][nt][2];
                tb[(R+8)*132 + C+1] = acc[mt][nt][3];
            }
    }
    __syncthreads();
    float* Cb = (w == 0) ? g_Q : (w == 1) ? g_K : g_V;
#pragma unroll
    for (int it = 0; it < 16; it++) {
        int v = tid + it * 256;
        int rr = v >> 5, c4 = (v & 31) * 4;
        float4 o = make_float4(tb[rr*132 + c4], tb[rr*132 + c4 + 1],
                               tb[rr*132 + c4 + 2], tb[rr*132 + c4 + 3]);
        *(float4*)(Cb + ((size_t)(m0 + rr) * MSEG + s) * DM + n0 + c4) = o;
    }
}

// ---------------- FC GEMM + bias + residual ----------------
// grid (4 ntiles, 768 mtiles), 256 threads. C = AO(98304x512) @ fcw^T
__global__ void __launch_bounds__(256, 2)
fc_mma_kernel(const float* __restrict__ fcb, float* __restrict__ outp)
{
    extern __shared__ char smem[];
    const uint32_t sb = smem_u32(smem);
    const int tid = threadIdx.x, wid = tid >> 5, lane = tid & 31;
    const int wm = wid & 3, wn = wid >> 2;
    const int n0 = blockIdx.x * 128;
    const int m0 = blockIdx.y * 128;
    const int nc = 32;                       // K = 512

    const char* Ah = (const char*)(g_AOh + (size_t)m0 * DM);
    const char* Al = (const char*)(g_AOl + (size_t)m0 * DM);
    const char* Bh = (const char*)(g_FWh + (size_t)n0 * DM);
    const char* Bl = (const char*)(g_FWl + (size_t)n0 * DM);
    const size_t strA = (size_t)DM * 2, strB = (size_t)DM * 2;

    uint32_t aoff, boff;
    ldm_offsets(wm, wn, lane, aoff, boff);

    float acc[2][8][4];
#pragma unroll
    for (int i = 0; i < 2; i++)
#pragma unroll
        for (int j = 0; j < 8; j++)
#pragma unroll
            for (int k = 0; k < 4; k++) acc[i][j][k] = 0.0f;

    gemm_mainloop(sb, tid, nc, Ah, Al, strA, Bh, Bl, strB, aoff, boff, acc);

    float* tb = (float*)smem;
    {
        const int l4 = lane >> 2, lm = lane & 3;
#pragma unroll
        for (int mt = 0; mt < 2; mt++)
#pragma unroll
            for (int nt = 0; nt < 8; nt++) {
                int R = wm*32 + mt*16 + l4;
                int C = wn*64 + nt*8 + lm*2;
                tb[R*132 + C]       = acc[mt][nt][0];
                tb[R*132 + C + 1]   = acc[mt][nt][1];
                tb[(R+8)*132 + C]   = acc[mt][nt][2];
                tb[(R+8)*132 + C+1] = acc[mt][nt][3];
            }
    }
    __syncthreads();
#pragma unroll
    for (int it = 0; it < 16; it++) {
        int v = tid + it * 256;
        int rr = v >> 5, c4 = (v & 31) * 4;
        int m = m0 + rr, n = n0 + c4;
        float4 bb = *(const float4*)(fcb + n);
        float4 vv = *(const float4*)(g_V + (size_t)m * DM + n);
        float4 o;
        o.x = tb[rr*132 + c4]     + bb.x + vv.x;
        o.y = tb[rr*132 + c4 + 1] + bb.y + vv.y;
        o.z = tb[rr*132 + c4 + 2] + bb.z + vv.z;
        o.w = tb[rr*132 + c4 + 3] + bb.w + vv.w;
        *(float4*)(outp + (size_t)m * DM + n) = o;
    }
}

// ---------------- attention logits + global min ----------------
__global__ void __launch_bounds__(256)
attn_logits_kernel()
{
    const int b    = blockIdx.x;
    const int h    = threadIdx.x >> 5;
    const int lane = threadIdx.x & 31;

    const float* Qb = g_Q + (size_t)b * (MSEG*DM) + h * 64 + lane;
    const float* Kb = g_K + (size_t)b * (MSEG*DM) + h * 64 + lane;

    float q0[6], q1[6], k0v[6], k1v[6];
#pragma unroll
    for (int t = 0; t < 6; t++) {
        q0[t]  = Qb[t*DM];  q1[t]  = Qb[t*DM + 32];
        k0v[t] = Kb[t*DM];  k1v[t] = Kb[t*DM + 32];
    }

    float lmin = 3.4e38f;
    float* lp = g_logits + ((size_t)b * NH + h) * 36;
#pragma unroll
    for (int tq = 0; tq < 6; tq++) {
#pragma unroll
        for (int tk = 0; tk < 6; tk++) {
            float p = q0[tq]*k0v[tk] + q1[tq]*k1v[tk];
#pragma unroll
            for (int o = 16; o > 0; o >>= 1)
                p += __shfl_xor_sync(0xffffffffu, p, o);
            p *= INV_TEMP;
            if (lane == 0) {
                lp[tq*6 + tk] = p;
                lmin = fminf(lmin, p);
            }
        }
    }
    if (lane == 0) atomicMin(&g_min_bits, fenc(lmin));
}

// ---------------- finalize attention + attn@V (writes AO hi/lo bf16) ----------------
__global__ void __launch_bounds__(256)
attn_finalize_kernel(float* __restrict__ attn_out)
{
    const int b   = blockIdx.x;
    const int tid = threadIdx.x;
    __shared__ float at[NH*36];
    __shared__ float s_scale;

    if (tid == 0) s_scale = 1.0f / fabsf(fdec(g_min_bits));
    __syncthreads();
    const float scale = s_scale;

    if (tid < 48) {
        int h = tid / 6, tq = tid % 6;
        const float* lp = g_logits + ((size_t)b * NH + h) * 36 + tq * 6;
        float v[6]; float ss = 0.0f;
#pragma unroll
        for (int k = 0; k < 6; k++) { v[k] = lp[k] * scale; ss += v[k]*v[k]; }
        float inorm = 1.0f / fmaxf(sqrtf(ss), 1e-12f);
        float mx = -3.4e38f;
#pragma unroll
        for (int k = 0; k < 6; k++) { v[k] *= inorm; mx = fmaxf(mx, v[k]); }
        float es = 0.0f; float e[6];
#pragma unroll
        for (int k = 0; k < 6; k++) { e[k] = expf(v[k] - mx); es += e[k]; }
        float r = 1.0f / es;
        float* ao = attn_out + ((size_t)b * NH + h) * 36 + tq * 6;
#pragma unroll
        for (int k = 0; k < 6; k++) {
            float a = e[k] * r;
            at[h*36 + tq*6 + k] = a;
            ao[k] = a;
        }
    }
    __syncthreads();

    const float* Vb = g_V + (size_t)b * (MSEG*DM);
    size_t base = (size_t)b * (MSEG*DM);
    for (int idx = tid; idx < MSEG*DM; idx += 256) {
        int t = idx >> 9;
        int f = idx & 511;
        int h = f >> 6;
        const float* ar = &at[h*36 + t*6];
        float sv = 0.0f;
#pragma unroll
        for (int k = 0; k < 6; k++) sv += ar[k] * Vb[k*DM + f];
        __nv_bfloat16 hi = __float2bfloat16_rn(sv);
        g_AOh[base + idx] = hi;
        g_AOl[base + idx] = __float2bfloat16_rn(sv - __bfloat162float(hi));
    }
}

// ---------------- LayerNorm ----------------
__global__ void __launch_bounds__(128)
ln_kernel(float* __restrict__ outp, const float* __restrict__ g,
          const float* __restrict__ be)
{
    const int row = blockIdx.x;
    float* p = outp + (size_t)row * DM;
    const int tid = threadIdx.x;

    float4 x = *(const float4*)(p + tid * 4);
    float s  = x.x + x.y + x.z + x.w;
    float sq = x.x*x.x + x.y*x.y + x.z*x.z + x.w*x.w;

#pragma unroll
    for (int o = 16; o > 0; o >>= 1) {
        s  += __shfl_xor_sync(0xffffffffu, s,  o);
        sq += __shfl_xor_sync(0xffffffffu, sq, o);
    }
    __shared__ float ws[4], wq[4];
    int w = tid >> 5, lane = tid & 31;
    if (lane == 0) { ws[w] = s; wq[w] = sq; }
    __syncthreads();
    s  = ws[0] + ws[1] + ws[2] + ws[3];
    sq = wq[0] + wq[1] + wq[2] + wq[3];

    float mu  = s * (1.0f / DM);
    float var = sq * (1.0f / DM) - mu * mu;
    float rstd = rsqrtf(var + LN_EPS);

    int c = tid * 4;
    float4 gg = *(const float4*)(g + c);
    float4 bb = *(const float4*)(be + c);
    float4 o;
    o.x = (x.x - mu) * rstd * gg.x + bb.x;
    o.y = (x.y - mu) * rstd * gg.y + bb.y;
    o.z = (x.z - mu) * rstd * gg.z + bb.z;
    o.w = (x.w - mu) * rstd * gg.w + bb.w;
    *(float4*)(p + c) = o;
}

// ---------------- launch ----------------
extern "C" void kernel_launch(void* const* d_in, const int* in_sizes, int n_in,
                              void* d_out, int out_size)
{
    const float* inp = (const float*)d_in[0];
    WPtrs P;
    for (int i = 0; i < 18; i++) P.w[i] = (const float*)d_in[1 + i];
    const float* fc_w = (const float*)d_in[19];
    const float* fc_b = (const float*)d_in[20];
    const float* ln_g = (const float*)d_in[21];
    const float* ln_b = (const float*)d_in[22];

    float* outp     = (float*)d_out;
    float* attn_out = outp + (size_t)NROWS * DM;

    cudaFuncSetAttribute(qkv_mma_kernel, cudaFuncAttributeMaxDynamicSharedMemorySize, GEMM_SMEM);
    cudaFuncSetAttribute(fc_mma_kernel,  cudaFuncAttributeMaxDynamicSharedMemorySize, GEMM_SMEM);

    conv_input_kernel<<<(BS*(size_t)DIN/4 + 255)/256, 256>>>(inp);
    conv_w_kernel<<<dim3(1024, 18), 256>>>(P);
    conv_fcw_kernel<<<256, 256>>>(fc_w);
    qkv_mma_kernel<<<dim3(4, 128, 18), 256, GEMM_SMEM>>>();
    attn_logits_kernel<<<BS, 256>>>();
    attn_finalize_kernel<<<BS, 256>>>(attn_out);
    fc_mma_kernel<<<dim3(4, 768), 256, GEMM_SMEM>>>(fc_b, outp);
    ln_kernel<<<NROWS, 128>>>(outp, ln_g, ln_b);
}

// round 10
// speedup vs baseline: 1.2801x; 1.2801x over previous
#include <cuda_runtime.h>
#include <cuda_bf16.h>
#include <cstdint>

// ---------------- problem constants ----------------
#define BS     16384
#define MSEG   6
#define DM     512
#define NH     8
#define DIN    6144
#define NROWS  (BS*MSEG)            // 98304
#define QKV_ELEMS (NROWS*DM)        // 50331648
#define NLOGITS (BS*NH*36)
#define INV_TEMP 0.125f
#define LN_EPS 1e-6f
#define WPACK  9437184              // 512*6144*3

// ---------------- scratch ----------------
__device__ float g_Q[QKV_ELEMS];
__device__ float g_K[QKV_ELEMS];
__device__ float g_V[QKV_ELEMS];
__device__ float g_logits[NLOGITS];
__device__ unsigned g_min_bits;
__device__ __nv_bfloat16 g_Ah[(size_t)BS*DIN];
__device__ __nv_bfloat16 g_Al[(size_t)BS*DIN];
__device__ __nv_bfloat16 g_Wh[WPACK];
__device__ __nv_bfloat16 g_Wl[WPACK];
__device__ __nv_bfloat16 g_FWh[DM*DM];
__device__ __nv_bfloat16 g_FWl[DM*DM];
__device__ __nv_bfloat16 g_AOh[QKV_ELEMS];
__device__ __nv_bfloat16 g_AOl[QKV_ELEMS];

// combo c = s*3 + w  (w: 0=q, 1=k, 2=v)
__constant__ int c_cK[18]   = {2048,2048,2048,1024,1024,1024,512,512,512,
                               1536,1536,1536,768,768,768,256,256,256};
__constant__ int c_cOff[18] = {0,0,0,2048,2048,2048,3072,3072,3072,
                               3584,3584,3584,5120,5120,5120,5888,5888,5888};
__constant__ int c_cW[18]   = {0,1048576,2097152,3145728,3670016,4194304,
                               4718592,4980736,5242880,5505024,6291456,7077888,
                               7864320,8257536,8650752,9043968,9175040,9306112};

struct WPtrs { const float* w[18]; };

// ---------------- helpers ----------------
__device__ __forceinline__ uint32_t smem_u32(const void* p) {
    uint32_t a;
    asm("{ .reg .u64 t; cvta.to.shared.u64 t, %1; cvt.u32.u64 %0, t; }" : "=r"(a) : "l"(p));
    return a;
}
__device__ __forceinline__ void cpa16(uint32_t s, const void* g) {
    asm volatile("cp.async.cg.shared.global [%0], [%1], 16;" :: "r"(s), "l"(g));
}
__device__ __forceinline__ void cpa_commit() { asm volatile("cp.async.commit_group;" ::: "memory"); }
__device__ __forceinline__ void cpa_wait1()  { asm volatile("cp.async.wait_group 1;" ::: "memory"); }

__device__ __forceinline__ void mma16816(float* c, const uint32_t* a, const uint32_t* b) {
    asm volatile(
        "mma.sync.aligned.m16n8k16.row.col.f32.bf16.bf16.f32 "
        "{%0,%1,%2,%3}, {%4,%5,%6,%7}, {%8,%9}, {%0,%1,%2,%3};"
        : "+f"(c[0]), "+f"(c[1]), "+f"(c[2]), "+f"(c[3])
        : "r"(a[0]), "r"(a[1]), "r"(a[2]), "r"(a[3]), "r"(b[0]), "r"(b[1]));
}
__device__ __forceinline__ void ldm_x4(uint32_t* r, uint32_t addr) {
    asm volatile("ldmatrix.sync.aligned.m8n8.x4.shared.b16 {%0,%1,%2,%3}, [%4];"
        : "=r"(r[0]), "=r"(r[1]), "=r"(r[2]), "=r"(r[3]) : "r"(addr));
}

// ---------------- min encoding ----------------
__device__ __forceinline__ unsigned fenc(float f) {
    unsigned u = __float_as_uint(f);
    return (u & 0x80000000u) ? ~u : (u | 0x80000000u);
}
__device__ __forceinline__ float fdec(unsigned e) {
    unsigned u = (e & 0x80000000u) ? (e & 0x7fffffffu) : ~e;
    return __uint_as_float(u);
}

// ---------------- conversion kernels ----------------
__device__ __forceinline__ void split4(float4 x, __nv_bfloat16* h, __nv_bfloat16* l) {
    float v[4] = {x.x, x.y, x.z, x.w};
#pragma unroll
    for (int i = 0; i < 4; i++) {
        __nv_bfloat16 hi = __float2bfloat16_rn(v[i]);
        h[i] = hi;
        l[i] = __float2bfloat16_rn(v[i] - __bfloat162float(hi));
    }
}

__global__ void __launch_bounds__(256) conv_input_kernel(const float* __restrict__ inp) {
    size_t i = (size_t)blockIdx.x * 256 + threadIdx.x;   // float4 index
    if (i == 0) g_min_bits = 0xFFFFFFFFu;
    float4 x = ((const float4*)inp)[i];
    __nv_bfloat16 h[4], l[4];
    split4(x, h, l);
#pragma unroll
    for (int j = 0; j < 4; j++) { g_Ah[i*4+j] = h[j]; g_Al[i*4+j] = l[j]; }
}

__global__ void __launch_bounds__(256) conv_w_kernel(WPtrs P) {
    int c = blockIdx.y;
    int n4 = (512 * c_cK[c]) >> 2;
    int i = blockIdx.x * 256 + threadIdx.x;
    if (i >= n4) return;
    float4 x = ((const float4*)P.w[c])[i];
    __nv_bfloat16 h[4], l[4];
    split4(x, h, l);
    size_t base = (size_t)c_cW[c] + (size_t)i * 4;
#pragma unroll
    for (int j = 0; j < 4; j++) { g_Wh[base+j] = h[j]; g_Wl[base+j] = l[j]; }
}

__global__ void __launch_bounds__(256) conv_fcw_kernel(const float* __restrict__ fcw) {
    int i = blockIdx.x * 256 + threadIdx.x;   // 65536 float4s
    float4 x = ((const float4*)fcw)[i];
    __nv_bfloat16 h[4], l[4];
    split4(x, h, l);
#pragma unroll
    for (int j = 0; j < 4; j++) { g_FWh[i*4+j] = h[j]; g_FWl[i*4+j] = l[j]; }
}

// ---------------- mma.sync GEMM configuration ----------------
// CTA tile 128x128, BK=32 bf16, 3-stage ring, 2 CTAs/SM, ONE barrier per iter.
// smem buffer: 128 rows x 64B, XOR swizzle: chunk c (16B) stored at c ^ ((r>>1)&3).
// ldmatrix conflict-free: phase 64*(r&1) + 16*(c^((r>>1)&3)) distinct over 8 rows.
#define BUFB   8192               // bytes per buffer (128*64)
#define STAGE_BYTES (4*BUFB)      // 32768  [Ah|Al|Bh|Bl]
#define GEMM_SMEM (3*STAGE_BYTES) // 98304

// one stage: 512 chunks per buffer, 256 threads -> 2 per thread per buffer
__device__ __forceinline__ void load_stage_g(
    uint32_t sbase, int tid,
    const char* Ah, const char* Al, size_t strA,
    const char* Bh, const char* Bl, size_t strB, size_t kb)
{
#pragma unroll
    for (int j = 0; j < 2; j++) {
        int q = tid + j * 256;
        int r = q >> 2, cc = q & 3;
        uint32_t so = (uint32_t)(r * 64 + ((cc ^ ((r >> 1) & 3)) << 4));
        size_t ga = (size_t)r * strA + kb + cc * 16;
        size_t gb = (size_t)r * strB + kb + cc * 16;
        cpa16(sbase + so,            Ah + ga);
        cpa16(sbase + BUFB + so,     Al + ga);
        cpa16(sbase + 2*BUFB + so,   Bh + gb);
        cpa16(sbase + 3*BUFB + so,   Bl + gb);
    }
    cpa_commit();
}

// per-lane ldmatrix base offsets (swizzle key invariant under +16-row steps)
__device__ __forceinline__ void ldm_offsets(int wm, int wn, int lane,
                                            uint32_t& aoff, uint32_t& boff)
{
    int g = lane >> 3, r8 = lane & 7;
    int arow = wm * 32 + r8 + (g & 1) * 8;        // mt=0 row
    int ach  = g >> 1;                             // chunk 0/1 (k-half)
    aoff = (uint32_t)(arow * 64 + ((ach ^ ((arow >> 1) & 3)) << 4));
    int brow = wn * 64 + r8 + (g >> 1) * 8;        // p=0 row
    int bch  = g & 1;
    boff = (uint32_t)(brow * 64 + ((bch ^ ((brow >> 1) & 3)) << 4));
}

// compute one BK=32 stage: 24 ldmatrix + 96 HMMA per warp
__device__ __forceinline__ void compute_stage(
    uint32_t sstage, uint32_t aoff, uint32_t boff, float acc[2][8][4])
{
    const uint32_t Ah_ = sstage,            Al_ = sstage + BUFB;
    const uint32_t Bh_ = sstage + 2*BUFB,   Bl_ = sstage + 3*BUFB;

#pragma unroll
    for (int k16 = 0; k16 < 2; k16++) {
        const uint32_t kx = k16 << 5;              // chunk+2 == XOR 32 in swizzled addr
        uint32_t ah[2][4], al[2][4];
#pragma unroll
        for (int mt = 0; mt < 2; mt++) {
            ldm_x4(ah[mt], Ah_ + (aoff ^ kx) + mt * 1024);
            ldm_x4(al[mt], Al_ + (aoff ^ kx) + mt * 1024);
        }
#pragma unroll
        for (int p = 0; p < 4; p++) {
            uint32_t bh[4], bl[4];
            ldm_x4(bh, Bh_ + (boff ^ kx) + p * 1024);
            ldm_x4(bl, Bl_ + (boff ^ kx) + p * 1024);
#pragma unroll
            for (int mt = 0; mt < 2; mt++) {
                mma16816(acc[mt][2*p],   ah[mt], bh);
                mma16816(acc[mt][2*p+1], ah[mt], bh + 2);
                mma16816(acc[mt][2*p],   ah[mt], bl);
                mma16816(acc[mt][2*p+1], ah[mt], bl + 2);
                mma16816(acc[mt][2*p],   al[mt], bh);
                mma16816(acc[mt][2*p+1], al[mt], bh + 2);
            }
        }
    }
}

// 3-stage ring mainloop, one barrier per iteration
__device__ __forceinline__ void gemm_mainloop(
    uint32_t sb, int tid, int nc,
    const char* Ah, const char* Al, size_t strA,
    const char* Bh, const char* Bl, size_t strB,
    uint32_t aoff, uint32_t boff, float acc[2][8][4])
{
    load_stage_g(sb,               tid, Ah, Al, strA, Bh, Bl, strB, 0);
    load_stage_g(sb + STAGE_BYTES, tid, Ah, Al, strA, Bh, Bl, strB, 64);

    uint32_t stg = 0;                      // i % 3
    for (int i = 0; i < nc; i++) {
        cpa_wait1();                        // stage i landed (i+1 may be in flight)
        __syncthreads();                    // all warps done with stage i-1 (== (i+2)%3)
        if (i + 2 < nc) {
            uint32_t nstg = stg + 2; if (nstg >= 3) nstg -= 3;
            load_stage_g(sb + nstg * STAGE_BYTES, tid,
                         Ah, Al, strA, Bh, Bl, strB, (size_t)(i+2) * 64);
        } else {
            cpa_commit();                   // keep wait_group accounting exact
        }
        compute_stage(sb + stg * STAGE_BYTES, aoff, boff, acc);
        if (++stg == 3) stg = 0;
    }
    __syncthreads();
}

// ---------------- QKV GEMM ----------------
// grid (4 ntiles, 128 mtiles, 18 combos), 256 threads.
__global__ void __launch_bounds__(256, 2)
qkv_mma_kernel()
{
    extern __shared__ char smem[];
    const uint32_t sb = smem_u32(smem);
    const int tid = threadIdx.x, wid = tid >> 5, lane = tid & 31;
    const int wm = wid & 3, wn = wid >> 2;
    const int n0 = blockIdx.x * 128;
    const int m0 = blockIdx.y * 128;
    const int c  = blockIdx.z;
    const int Kdim = c_cK[c];
    const int seg  = c_cOff[c];
    const int s = c / 3, w = c % 3;
    const int nc = Kdim >> 5;

    const char* Ah = (const char*)(g_Ah + (size_t)m0 * DIN + seg);
    const char* Al = (const char*)(g_Al + (size_t)m0 * DIN + seg);
    const char* Bh = (const char*)(g_Wh + (size_t)c_cW[c] + (size_t)n0 * Kdim);
    const char* Bl = (const char*)(g_Wl + (size_t)c_cW[c] + (size_t)n0 * Kdim);
    const size_t strA = (size_t)DIN * 2, strB = (size_t)Kdim * 2;

    uint32_t aoff, boff;
    ldm_offsets(wm, wn, lane, aoff, boff);

    float acc[2][8][4];
#pragma unroll
    for (int i = 0; i < 2; i++)
#pragma unroll
        for (int j = 0; j < 8; j++)
#pragma unroll
            for (int k = 0; k < 4; k++) acc[i][j][k] = 0.0f;

    gemm_mainloop(sb, tid, nc, Ah, Al, strA, Bh, Bl, strB, aoff, boff, acc);

    // epilogue: acc -> smem (128 x 132 fp32) -> coalesced global
    float* tb = (float*)smem;
    {
        const int l4 = lane >> 2, lm = lane & 3;
#pragma unroll
        for (int mt = 0; mt < 2; mt++)
#pragma unroll
            for (int nt = 0; nt < 8; nt++) {
                int R = wm*32 + mt*16 + l4;
                int C = wn*64 + nt*8 + lm*2;
                tb[R*132 + C]       = acc[mt][nt][0];
                tb[R*132 + C + 1]   = acc[mt][nt][1];
                tb[(R+8)*132 + C]   = acc[mt][nt][2];
                tb[(R+8)*132 + C+1] = acc[mt][nt][3];
            }
    }
    __syncthreads();
    float* Cb = (w == 0) ? g_Q : (w == 1) ? g_K : g_V;
#pragma unroll
    for (int it = 0; it < 16; it++) {
        int v = tid + it * 256;
        int rr = v >> 5, c4 = (v & 31) * 4;
        float4 o = make_float4(tb[rr*132 + c4], tb[rr*132 + c4 + 1],
                               tb[rr*132 + c4 + 2], tb[rr*132 + c4 + 3]);
        *(float4*)(Cb + ((size_t)(m0 + rr) * MSEG + s) * DM + n0 + c4) = o;
    }
}

// ---------------- FC GEMM + bias + residual ----------------
// grid (4 ntiles, 768 mtiles), 256 threads. C = AO(98304x512) @ fcw^T
__global__ void __launch_bounds__(256, 2)
fc_mma_kernel(const float* __restrict__ fcb, float* __restrict__ outp)
{
    extern __shared__ char smem[];
    const uint32_t sb = smem_u32(smem);
    const int tid = threadIdx.x, wid = tid >> 5, lane = tid & 31;
    const int wm = wid & 3, wn = wid >> 2;
    const int n0 = blockIdx.x * 128;
    const int m0 = blockIdx.y * 128;
    const int nc = 16;                       // K = 512

    const char* Ah = (const char*)(g_AOh + (size_t)m0 * DM);
    const char* Al = (const char*)(g_AOl + (size_t)m0 * DM);
    const char* Bh = (const char*)(g_FWh + (size_t)n0 * DM);
    const char* Bl = (const char*)(g_FWl + (size_t)n0 * DM);
    const size_t strA = (size_t)DM * 2, strB = (size_t)DM * 2;

    uint32_t aoff, boff;
    ldm_offsets(wm, wn, lane, aoff, boff);

    float acc[2][8][4];
#pragma unroll
    for (int i = 0; i < 2; i++)
#pragma unroll
        for (int j = 0; j < 8; j++)
#pragma unroll
            for (int k = 0; k < 4; k++) acc[i][j][k] = 0.0f;

    gemm_mainloop(sb, tid, nc, Ah, Al, strA, Bh, Bl, strB, aoff, boff, acc);

    float* tb = (float*)smem;
    {
        const int l4 = lane >> 2, lm = lane & 3;
#pragma unroll
        for (int mt = 0; mt < 2; mt++)
#pragma unroll
            for (int nt = 0; nt < 8; nt++) {
                int R = wm*32 + mt*16 + l4;
                int C = wn*64 + nt*8 + lm*2;
                tb[R*132 + C]       = acc[mt][nt][0];
                tb[R*132 + C + 1]   = acc[mt][nt][1];
                tb[(R+8)*132 + C]   = acc[mt][nt][2];
                tb[(R+8)*132 + C+1] = acc[mt][nt][3];
            }
    }
    __syncthreads();
#pragma unroll
    for (int it = 0; it < 16; it++) {
        int v = tid + it * 256;
        int rr = v >> 5, c4 = (v & 31) * 4;
        int m = m0 + rr, n = n0 + c4;
        float4 bb = *(const float4*)(fcb + n);
        float4 vv = *(const float4*)(g_V + (size_t)m * DM + n);
        float4 o;
        o.x = tb[rr*132 + c4]     + bb.x + vv.x;
        o.y = tb[rr*132 + c4 + 1] + bb.y + vv.y;
        o.z = tb[rr*132 + c4 + 2] + bb.z + vv.z;
        o.w = tb[rr*132 + c4 + 3] + bb.w + vv.w;
        *(float4*)(outp + (size_t)m * DM + n) = o;
    }
}

// ---------------- attention logits + global min ----------------
__global__ void __launch_bounds__(256)
attn_logits_kernel()
{
    const int b    = blockIdx.x;
    const int h    = threadIdx.x >> 5;
    const int lane = threadIdx.x & 31;

    const float* Qb = g_Q + (size_t)b * (MSEG*DM) + h * 64 + lane;
    const float* Kb = g_K + (size_t)b * (MSEG*DM) + h * 64 + lane;

    float q0[6], q1[6], k0v[6], k1v[6];
#pragma unroll
    for (int t = 0; t < 6; t++) {
        q0[t]  = Qb[t*DM];  q1[t]  = Qb[t*DM + 32];
        k0v[t] = Kb[t*DM];  k1v[t] = Kb[t*DM + 32];
    }

    float lmin = 3.4e38f;
    float* lp = g_logits + ((size_t)b * NH + h) * 36;
#pragma unroll
    for (int tq = 0; tq < 6; tq++) {
#pragma unroll
        for (int tk = 0; tk < 6; tk++) {
            float p = q0[tq]*k0v[tk] + q1[tq]*k1v[tk];
#pragma unroll
            for (int o = 16; o > 0; o >>= 1)
                p += __shfl_xor_sync(0xffffffffu, p, o);
            p *= INV_TEMP;
            if (lane == 0) {
                lp[tq*6 + tk] = p;
                lmin = fminf(lmin, p);
            }
        }
    }
    if (lane == 0) atomicMin(&g_min_bits, fenc(lmin));
}

// ---------------- finalize attention + attn@V (writes AO hi/lo bf16) ----------------
__global__ void __launch_bounds__(256)
attn_finalize_kernel(float* __restrict__ attn_out)
{
    const int b   = blockIdx.x;
    const int tid = threadIdx.x;
    __shared__ float at[NH*36];
    __shared__ float s_scale;

    if (tid == 0) s_scale = 1.0f / fabsf(fdec(g_min_bits));
    __syncthreads();
    const float scale = s_scale;

    if (tid < 48) {
        int h = tid / 6, tq = tid % 6;
        const float* lp = g_logits + ((size_t)b * NH + h) * 36 + tq * 6;
        float v[6]; float ss = 0.0f;
#pragma unroll
        for (int k = 0; k < 6; k++) { v[k] = lp[k] * scale; ss += v[k]*v[k]; }
        float inorm = 1.0f / fmaxf(sqrtf(ss), 1e-12f);
        float mx = -3.4e38f;
#pragma unroll
        for (int k = 0; k < 6; k++) { v[k] *= inorm; mx = fmaxf(mx, v[k]); }
        float es = 0.0f; float e[6];
#pragma unroll
        for (int k = 0; k < 6; k++) { e[k] = expf(v[k] - mx); es += e[k]; }
        float r = 1.0f / es;
        float* ao = attn_out + ((size_t)b * NH + h) * 36 + tq * 6;
#pragma unroll
        for (int k = 0; k < 6; k++) {
            float a = e[k] * r;
            at[h*36 + tq*6 + k] = a;
            ao[k] = a;
        }
    }
    __syncthreads();

    const float* Vb = g_V + (size_t)b * (MSEG*DM);
    size_t base = (size_t)b * (MSEG*DM);
    for (int idx = tid; idx < MSEG*DM; idx += 256) {
        int t = idx >> 9;
        int f = idx & 511;
        int h = f >> 6;
        const float* ar = &at[h*36 + t*6];
        float sv = 0.0f;
#pragma unroll
        for (int k = 0; k < 6; k++) sv += ar[k] * Vb[k*DM + f];
        __nv_bfloat16 hi = __float2bfloat16_rn(sv);
        g_AOh[base + idx] = hi;
        g_AOl[base + idx] = __float2bfloat16_rn(sv - __bfloat162float(hi));
    }
}

// ---------------- LayerNorm ----------------
__global__ void __launch_bounds__(128)
ln_kernel(float* __restrict__ outp, const float* __restrict__ g,
          const float* __restrict__ be)
{
    const int row = blockIdx.x;
    float* p = outp + (size_t)row * DM;
    const int tid = threadIdx.x;

    float4 x = *(const float4*)(p + tid * 4);
    float s  = x.x + x.y + x.z + x.w;
    float sq = x.x*x.x + x.y*x.y + x.z*x.z + x.w*x.w;

#pragma unroll
    for (int o = 16; o > 0; o >>= 1) {
        s  += __shfl_xor_sync(0xffffffffu, s,  o);
        sq += __shfl_xor_sync(0xffffffffu, sq, o);
    }
    __shared__ float ws[4], wq[4];
    int w = tid >> 5, lane = tid & 31;
    if (lane == 0) { ws[w] = s; wq[w] = sq; }
    __syncthreads();
    s  = ws[0] + ws[1] + ws[2] + ws[3];
    sq = wq[0] + wq[1] + wq[2] + wq[3];

    float mu  = s * (1.0f / DM);
    float var = sq * (1.0f / DM) - mu * mu;
    float rstd = rsqrtf(var + LN_EPS);

    int c = tid * 4;
    float4 gg = *(const float4*)(g + c);
    float4 bb = *(const float4*)(be + c);
    float4 o;
    o.x = (x.x - mu) * rstd * gg.x + bb.x;
    o.y = (x.y - mu) * rstd * gg.y + bb.y;
    o.z = (x.z - mu) * rstd * gg.z + bb.z;
    o.w = (x.w - mu) * rstd * gg.w + bb.w;
    *(float4*)(p + c) = o;
}

// ---------------- launch ----------------
extern "C" void kernel_launch(void* const* d_in, const int* in_sizes, int n_in,
                              void* d_out, int out_size)
{
    const float* inp = (const float*)d_in[0];
    WPtrs P;
    for (int i = 0; i < 18; i++) P.w[i] = (const float*)d_in[1 + i];
    const float* fc_w = (const float*)d_in[19];
    const float* fc_b = (const float*)d_in[20];
    const float* ln_g = (const float*)d_in[21];
    const float* ln_b = (const float*)d_in[22];

    float* outp     = (float*)d_out;
    float* attn_out = outp + (size_t)NROWS * DM;

    cudaFuncSetAttribute(qkv_mma_kernel, cudaFuncAttributeMaxDynamicSharedMemorySize, GEMM_SMEM);
    cudaFuncSetAttribute(fc_mma_kernel,  cudaFuncAttributeMaxDynamicSharedMemorySize, GEMM_SMEM);

    conv_input_kernel<<<(BS*(size_t)DIN/4 + 255)/256, 256>>>(inp);
    conv_w_kernel<<<dim3(1024, 18), 256>>>(P);
    conv_fcw_kernel<<<256, 256>>>(fc_w);
    qkv_mma_kernel<<<dim3(4, 128, 18), 256, GEMM_SMEM>>>();
    attn_logits_kernel<<<BS, 256>>>();
    attn_finalize_kernel<<<BS, 256>>>(attn_out);
    fc_mma_kernel<<<dim3(4, 768), 256, GEMM_SMEM>>>(fc_b, outp);
    ln_kernel<<<NROWS, 128>>>(outp, ln_g, ln_b);
}

// round 12
// speedup vs baseline: 1.7218x; 1.3451x over previous
#include <cuda_runtime.h>
#include <cuda_fp16.h>
#include <cstdint>

// ---------------- problem constants ----------------
#define BS     16384
#define MSEG   6
#define DM     512
#define NH     8
#define DIN    6144
#define NROWS  (BS*MSEG)            // 98304
#define QKV_ELEMS (NROWS*DM)        // 50331648
#define INV_TEMP 0.125f
#define LN_EPS 1e-6f
#define WPACK  9437184              // 512*6144*3

// ---------------- scratch ----------------
__device__ float g_Q[QKV_ELEMS];
__device__ float g_K[QKV_ELEMS];
__device__ float g_V[QKV_ELEMS];
__device__ __half g_Ah[(size_t)BS*DIN];
__device__ __half g_Al[(size_t)BS*DIN];
__device__ __half g_W[WPACK];
__device__ __half g_FW[DM*DM];
__device__ __half g_AOh[QKV_ELEMS];
__device__ __half g_AOl[QKV_ELEMS];

// combo c = s*3 + w  (w: 0=q, 1=k, 2=v)
__constant__ int c_cK[18]   = {2048,2048,2048,1024,1024,1024,512,512,512,
                               1536,1536,1536,768,768,768,256,256,256};
__constant__ int c_cOff[18] = {0,0,0,2048,2048,2048,3072,3072,3072,
                               3584,3584,3584,5120,5120,5120,5888,5888,5888};
__constant__ int c_cW[18]   = {0,1048576,2097152,3145728,3670016,4194304,
                               4718592,4980736,5242880,5505024,6291456,7077888,
                               7864320,8257536,8650752,9043968,9175040,9306112};

struct WPtrs { const float* w[18]; };

// ---------------- helpers ----------------
__device__ __forceinline__ uint32_t smem_u32(const void* p) {
    uint32_t a;
    asm("{ .reg .u64 t; cvta.to.shared.u64 t, %1; cvt.u32.u64 %0, t; }" : "=r"(a) : "l"(p));
    return a;
}
__device__ __forceinline__ void cpa16(uint32_t s, const void* g) {
    asm volatile("cp.async.cg.shared.global [%0], [%1], 16;" :: "r"(s), "l"(g));
}
__device__ __forceinline__ void cpa_commit() { asm volatile("cp.async.commit_group;" ::: "memory"); }
__device__ __forceinline__ void cpa_wait1()  { asm volatile("cp.async.wait_group 1;" ::: "memory"); }

__device__ __forceinline__ void mma16816(float* c, const uint32_t* a, const uint32_t* b) {
    asm volatile(
        "mma.sync.aligned.m16n8k16.row.col.f32.f16.f16.f32 "
        "{%0,%1,%2,%3}, {%4,%5,%6,%7}, {%8,%9}, {%0,%1,%2,%3};"
        : "+f"(c[0]), "+f"(c[1]), "+f"(c[2]), "+f"(c[3])
        : "r"(a[0]), "r"(a[1]), "r"(a[2]), "r"(a[3]), "r"(b[0]), "r"(b[1]));
}
__device__ __forceinline__ void ldm_x4(uint32_t* r, uint32_t addr) {
    asm volatile("ldmatrix.sync.aligned.m8n8.x4.shared.b16 {%0,%1,%2,%3}, [%4];"
        : "=r"(r[0]), "=r"(r[1]), "=r"(r[2]), "=r"(r[3]) : "r"(addr));
}

// ---------------- conversion kernels ----------------
__global__ void __launch_bounds__(256) conv_input_kernel(const float* __restrict__ inp) {
    size_t i = (size_t)blockIdx.x * 256 + threadIdx.x;   // float4 index
    float4 x = ((const float4*)inp)[i];
    float v[4] = {x.x, x.y, x.z, x.w};
#pragma unroll
    for (int j = 0; j < 4; j++) {
        __half hi = __float2half_rn(v[j]);
        g_Ah[i*4+j] = hi;
        g_Al[i*4+j] = __float2half_rn(v[j] - __half2float(hi));
    }
}

__global__ void __launch_bounds__(256) conv_w_kernel(WPtrs P) {
    int c = blockIdx.y;
    int n4 = (512 * c_cK[c]) >> 2;
    int i = blockIdx.x * 256 + threadIdx.x;
    if (i >= n4) return;
    float4 x = ((const float4*)P.w[c])[i];
    size_t base = (size_t)c_cW[c] + (size_t)i * 4;
    g_W[base+0] = __float2half_rn(x.x);
    g_W[base+1] = __float2half_rn(x.y);
    g_W[base+2] = __float2half_rn(x.z);
    g_W[base+3] = __float2half_rn(x.w);
}

__global__ void __launch_bounds__(256) conv_fcw_kernel(const float* __restrict__ fcw) {
    int i = blockIdx.x * 256 + threadIdx.x;   // 65536 float4s
    float4 x = ((const float4*)fcw)[i];
    g_FW[i*4+0] = __float2half_rn(x.x);
    g_FW[i*4+1] = __float2half_rn(x.y);
    g_FW[i*4+2] = __float2half_rn(x.z);
    g_FW[i*4+3] = __float2half_rn(x.w);
}

// ---------------- mma.sync GEMM configuration ----------------
// CTA tile 128x128, BK=32 fp16, 3-stage ring, 2 CTAs/SM, one barrier per iter.
// 2-term split: C = Ah*B + Al*B   (A fp16 hi/lo, B single fp16)
// smem buffer: 128 rows x 64B, XOR swizzle: chunk c (16B) at c ^ ((r>>1)&3).
#define BUFB   8192               // bytes per buffer (128*64)
#define STAGE_BYTES (3*BUFB)      // 24576  [Ah|Al|B]
#define GEMM_SMEM (3*STAGE_BYTES) // 73728

// one stage: 512 chunks per buffer, 256 threads -> 2 per thread per buffer
__device__ __forceinline__ void load_stage_g(
    uint32_t sbase, int tid,
    const char* Ah, const char* Al, size_t strA,
    const char* B, size_t strB, size_t kb)
{
#pragma unroll
    for (int j = 0; j < 2; j++) {
        int q = tid + j * 256;
        int r = q >> 2, cc = q & 3;
        uint32_t so = (uint32_t)(r * 64 + ((cc ^ ((r >> 1) & 3)) << 4));
        size_t ga = (size_t)r * strA + kb + cc * 16;
        size_t gb = (size_t)r * strB + kb + cc * 16;
        cpa16(sbase + so,            Ah + ga);
        cpa16(sbase + BUFB + so,     Al + ga);
        cpa16(sbase + 2*BUFB + so,   B + gb);
    }
    cpa_commit();
}

// per-lane ldmatrix base offsets (swizzle key invariant under +16-row steps)
__device__ __forceinline__ void ldm_offsets(int wm, int wn, int lane,
                                            uint32_t& aoff, uint32_t& boff)
{
    int g = lane >> 3, r8 = lane & 7;
    int arow = wm * 32 + r8 + (g & 1) * 8;
    int ach  = g >> 1;
    aoff = (uint32_t)(arow * 64 + ((ach ^ ((arow >> 1) & 3)) << 4));
    int brow = wn * 64 + r8 + (g >> 1) * 8;
    int bch  = g & 1;
    boff = (uint32_t)(brow * 64 + ((bch ^ ((brow >> 1) & 3)) << 4));
}

// compute one BK=32 stage: 16 ldmatrix + 64 HMMA per warp
__device__ __forceinline__ void compute_stage(
    uint32_t sstage, uint32_t aoff, uint32_t boff, float acc[2][8][4])
{
    const uint32_t Ah_ = sstage, Al_ = sstage + BUFB, B_ = sstage + 2*BUFB;

#pragma unroll
    for (int k16 = 0; k16 < 2; k16++) {
        const uint32_t kx = k16 << 5;              // chunk+2 == XOR 32 in swizzled addr
        uint32_t ah[2][4], al[2][4];
#pragma unroll
        for (int mt = 0; mt < 2; mt++) {
            ldm_x4(ah[mt], Ah_ + (aoff ^ kx) + mt * 1024);
            ldm_x4(al[mt], Al_ + (aoff ^ kx) + mt * 1024);
        }
#pragma unroll
        for (int p = 0; p < 4; p++) {
            uint32_t bb[4];
            ldm_x4(bb, B_ + (boff ^ kx) + p * 1024);
#pragma unroll
            for (int mt = 0; mt < 2; mt++) {
                mma16816(acc[mt][2*p],   ah[mt], bb);
                mma16816(acc[mt][2*p+1], ah[mt], bb + 2);
                mma16816(acc[mt][2*p],   al[mt], bb);
                mma16816(acc[mt][2*p+1], al[mt], bb + 2);
            }
        }
    }
}

// 3-stage ring mainloop, one barrier per iteration
__device__ __forceinline__ void gemm_mainloop(
    uint32_t sb, int tid, int nc,
    const char* Ah, const char* Al, size_t strA,
    const char* B, size_t strB,
    uint32_t aoff, uint32_t boff, float acc[2][8][4])
{
    load_stage_g(sb,               tid, Ah, Al, strA, B, strB, 0);
    load_stage_g(sb + STAGE_BYTES, tid, Ah, Al, strA, B, strB, 64);

    uint32_t stg = 0;
    for (int i = 0; i < nc; i++) {
        cpa_wait1();
        __syncthreads();
        if (i + 2 < nc) {
            uint32_t nstg = stg + 2; if (nstg >= 3) nstg -= 3;
            load_stage_g(sb + nstg * STAGE_BYTES, tid,
                         Ah, Al, strA, B, strB, (size_t)(i+2) * 64);
        } else {
            cpa_commit();
        }
        compute_stage(sb + stg * STAGE_BYTES, aoff, boff, acc);
        if (++stg == 3) stg = 0;
    }
    __syncthreads();
}

// ---------------- QKV GEMM ----------------
// grid (4 ntiles, 128 mtiles, 18 combos), 256 threads.
__global__ void __launch_bounds__(256, 2)
qkv_mma_kernel()
{
    extern __shared__ char smem[];
    const uint32_t sb = smem_u32(smem);
    const int tid = threadIdx.x, wid = tid >> 5, lane = tid & 31;
    const int wm = wid & 3, wn = wid >> 2;
    const int n0 = blockIdx.x * 128;
    const int m0 = blockIdx.y * 128;
    const int c  = blockIdx.z;
    const int Kdim = c_cK[c];
    const int seg  = c_cOff[c];
    const int s = c / 3, w = c % 3;
    const int nc = Kdim >> 5;

    const char* Ah = (const char*)(g_Ah + (size_t)m0 * DIN + seg);
    const char* Al = (const char*)(g_Al + (size_t)m0 * DIN + seg);
    const char* B  = (const char*)(g_W + (size_t)c_cW[c] + (size_t)n0 * Kdim);
    const size_t strA = (size_t)DIN * 2, strB = (size_t)Kdim * 2;

    uint32_t aoff, boff;
    ldm_offsets(wm, wn, lane, aoff, boff);

    float acc[2][8][4];
#pragma unroll
    for (int i = 0; i < 2; i++)
#pragma unroll
        for (int j = 0; j < 8; j++)
#pragma unroll
            for (int k = 0; k < 4; k++) acc[i][j][k] = 0.0f;

    gemm_mainloop(sb, tid, nc, Ah, Al, strA, B, strB, aoff, boff, acc);

    // epilogue: acc -> smem (128 x 132 fp32) -> coalesced global
    float* tb = (float*)smem;
    {
        const int l4 = lane >> 2, lm = lane & 3;
#pragma unroll
        for (int mt = 0; mt < 2; mt++)
#pragma unroll
            for (int nt = 0; nt < 8; nt++) {
                int R = wm*32 + mt*16 + l4;
                int C = wn*64 + nt*8 + lm*2;
                tb[R*132 + C]       = acc[mt][nt][0];
                tb[R*132 + C + 1]   = acc[mt][nt][1];
                tb[(R+8)*132 + C]   = acc[mt][nt][2];
                tb[(R+8)*132 + C+1] = acc[mt][nt][3];
            }
    }
    __syncthreads();
    float* Cb = (w == 0) ? g_Q : (w == 1) ? g_K : g_V;
#pragma unroll
    for (int it = 0; it < 16; it++) {
        int v = tid + it * 256;
        int rr = v >> 5, c4 = (v & 31) * 4;
        float4 o = make_float4(tb[rr*132 + c4], tb[rr*132 + c4 + 1],
                               tb[rr*132 + c4 + 2], tb[rr*132 + c4 + 3]);
        *(float4*)(Cb + ((size_t)(m0 + rr) * MSEG + s) * DM + n0 + c4) = o;
    }
}

// ---------------- FC GEMM + bias + residual ----------------
// grid (4 ntiles, 768 mtiles), 256 threads. C = AO(98304x512) @ fcw^T
__global__ void __launch_bounds__(256, 2)
fc_mma_kernel(const float* __restrict__ fcb, float* __restrict__ outp)
{
    extern __shared__ char smem[];
    const uint32_t sb = smem_u32(smem);
    const int tid = threadIdx.x, wid = tid >> 5, lane = tid & 31;
    const int wm = wid & 3, wn = wid >> 2;
    const int n0 = blockIdx.x * 128;
    const int m0 = blockIdx.y * 128;
    const int nc = 16;                       // K = 512

    const char* Ah = (const char*)(g_AOh + (size_t)m0 * DM);
    const char* Al = (const char*)(g_AOl + (size_t)m0 * DM);
    const char* B  = (const char*)(g_FW + (size_t)n0 * DM);
    const size_t strA = (size_t)DM * 2, strB = (size_t)DM * 2;

    uint32_t aoff, boff;
    ldm_offsets(wm, wn, lane, aoff, boff);

    float acc[2][8][4];
#pragma unroll
    for (int i = 0; i < 2; i++)
#pragma unroll
        for (int j = 0; j < 8; j++)
#pragma unroll
            for (int k = 0; k < 4; k++) acc[i][j][k] = 0.0f;

    gemm_mainloop(sb, tid, nc, Ah, Al, strA, B, strB, aoff, boff, acc);

    float* tb = (float*)smem;
    {
        const int l4 = lane >> 2, lm = lane & 3;
#pragma unroll
        for (int mt = 0; mt < 2; mt++)
#pragma unroll
            for (int nt = 0; nt < 8; nt++) {
                int R = wm*32 + mt*16 + l4;
                int C = wn*64 + nt*8 + lm*2;
                tb[R*132 + C]       = acc[mt][nt][0];
                tb[R*132 + C + 1]   = acc[mt][nt][1];
                tb[(R+8)*132 + C]   = acc[mt][nt][2];
                tb[(R+8)*132 + C+1] = acc[mt][nt][3];
            }
    }
    __syncthreads();
#pragma unroll
    for (int it = 0; it < 16; it++) {
        int v = tid + it * 256;
        int rr = v >> 5, c4 = (v & 31) * 4;
        int m = m0 + rr, n = n0 + c4;
        float4 bb = *(const float4*)(fcb + n);
        float4 vv = *(const float4*)(g_V + (size_t)m * DM + n);
        float4 o;
        o.x = tb[rr*132 + c4]     + bb.x + vv.x;
        o.y = tb[rr*132 + c4 + 1] + bb.y + vv.y;
        o.z = tb[rr*132 + c4 + 2] + bb.z + vv.z;
        o.w = tb[rr*132 + c4 + 3] + bb.w + vv.w;
        *(float4*)(outp + (size_t)m * DM + n) = o;
    }
}

// ---------------- fused attention ----------------
// The reference scales all logits by 1/|global min| then L2-normalizes each
// row: v*s/||v*s|| == v/||v|| for s>0, so the global min cancels exactly and
// no cross-batch pass is needed.
// block = 256 threads (warp h = head h), grid = BS.
__global__ void __launch_bounds__(256)
attn_kernel(float* __restrict__ attn_out)
{
    const int b    = blockIdx.x;
    const int tid  = threadIdx.x;
    const int h    = tid >> 5;
    const int lane = tid & 31;

    __shared__ float at[NH*36];

    const float* Qb = g_Q + (size_t)b * (MSEG*DM) + h * 64 + lane;
    const float* Kb = g_K + (size_t)b * (MSEG*DM) + h * 64 + lane;

    float q0[6], q1[6], k0v[6], k1v[6];
#pragma unroll
    for (int t = 0; t < 6; t++) {
        q0[t]  = Qb[t*DM];  q1[t]  = Qb[t*DM + 32];
        k0v[t] = Kb[t*DM];  k1v[t] = Kb[t*DM + 32];
    }

#pragma unroll
    for (int tq = 0; tq < 6; tq++) {
#pragma unroll
        for (int tk = 0; tk < 6; tk++) {
            float p = q0[tq]*k0v[tk] + q1[tq]*k1v[tk];
#pragma unroll
            for (int o = 16; o > 0; o >>= 1)
                p += __shfl_xor_sync(0xffffffffu, p, o);
            if (lane == 0) at[h*36 + tq*6 + tk] = p * INV_TEMP;
        }
    }
    __syncthreads();

    if (tid < 48) {
        int hh = tid / 6, tq = tid % 6;
        float* lp = &at[hh*36 + tq*6];
        float v[6]; float ss = 0.0f;
#pragma unroll
        for (int k = 0; k < 6; k++) { v[k] = lp[k]; ss += v[k]*v[k]; }
        float inorm = 1.0f / fmaxf(sqrtf(ss), 1e-30f);
        float mx = -3.4e38f;
#pragma unroll
        for (int k = 0; k < 6; k++) { v[k] *= inorm; mx = fmaxf(mx, v[k]); }
        float es = 0.0f; float e[6];
#pragma unroll
        for (int k = 0; k < 6; k++) { e[k] = expf(v[k] - mx); es += e[k]; }
        float r = 1.0f / es;
        float* ao = attn_out + ((size_t)b * NH + hh) * 36 + tq * 6;
#pragma unroll
        for (int k = 0; k < 6; k++) {
            float a = e[k] * r;
            lp[k] = a;
            ao[k] = a;
        }
    }
    __syncthreads();

    // AO[b,t,f] = sum_k attn[h,t,k] * V[b,k,f],  f = h*64+d ; fp16 hi/lo split
    const float* Vb = g_V + (size_t)b * (MSEG*DM);
    size_t base = (size_t)b * (MSEG*DM);
    for (int idx = tid; idx < MSEG*DM; idx += 256) {
        int t = idx >> 9;
        int f = idx & 511;
        int hh = f >> 6;
        const float* ar = &at[hh*36 + t*6];
        float sv = 0.0f;
#pragma unroll
        for (int k = 0; k < 6; k++) sv += ar[k] * Vb[k*DM + f];
        __half hi = __float2half_rn(sv);
        g_AOh[base + idx] = hi;
        g_AOl[base + idx] = __float2half_rn(sv - __half2float(hi));
    }
}

// ---------------- LayerNorm ----------------
__global__ void __launch_bounds__(128)
ln_kernel(float* __restrict__ outp, const float* __restrict__ g,
          const float* __restrict__ be)
{
    const int row = blockIdx.x;
    float* p = outp + (size_t)row * DM;
    const int tid = threadIdx.x;

    float4 x = *(const float4*)(p + tid * 4);
    float s  = x.x + x.y + x.z + x.w;
    float sq = x.x*x.x + x.y*x.y + x.z*x.z + x.w*x.w;

#pragma unroll
    for (int o = 16; o > 0; o >>= 1) {
        s  += __shfl_xor_sync(0xffffffffu, s,  o);
        sq += __shfl_xor_sync(0xffffffffu, sq, o);
    }
    __shared__ float ws[4], wq[4];
    int w = tid >> 5, lane = tid & 31;
    if (lane == 0) { ws[w] = s; wq[w] = sq; }
    __syncthreads();
    s  = ws[0] + ws[1] + ws[2] + ws[3];
    sq = wq[0] + wq[1] + wq[2] + wq[3];

    float mu  = s * (1.0f / DM);
    float var = sq * (1.0f / DM) - mu * mu;
    float rstd = rsqrtf(var + LN_EPS);

    int c = tid * 4;
    float4 gg = *(const float4*)(g + c);
    float4 bb = *(const float4*)(be + c);
    float4 o;
    o.x = (x.x - mu) * rstd * gg.x + bb.x;
    o.y = (x.y - mu) * rstd * gg.y + bb.y;
    o.z = (x.z - mu) * rstd * gg.z + bb.z;
    o.w = (x.w - mu) * rstd * gg.w + bb.w;
    *(float4*)(p + c) = o;
}

// ---------------- launch ----------------
extern "C" void kernel_launch(void* const* d_in, const int* in_sizes, int n_in,
                              void* d_out, int out_size)
{
    const float* inp = (const float*)d_in[0];
    WPtrs P;
    for (int i = 0; i < 18; i++) P.w[i] = (const float*)d_in[1 + i];
    const float* fc_w = (const float*)d_in[19];
    const float* fc_b = (const float*)d_in[20];
    const float* ln_g = (const float*)d_in[21];
    const float* ln_b = (const float*)d_in[22];

    float* outp     = (float*)d_out;
    float* attn_out = outp + (size_t)NROWS * DM;

    cudaFuncSetAttribute(qkv_mma_kernel, cudaFuncAttributeMaxDynamicSharedMemorySize, GEMM_SMEM);
    cudaFuncSetAttribute(fc_mma_kernel,  cudaFuncAttributeMaxDynamicSharedMemorySize, GEMM_SMEM);

    conv_input_kernel<<<(BS*(size_t)DIN/4 + 255)/256, 256>>>(inp);
    conv_w_kernel<<<dim3(1024, 18), 256>>>(P);
    conv_fcw_kernel<<<256, 256>>>(fc_w);
    qkv_mma_kernel<<<dim3(4, 128, 18), 256, GEMM_SMEM>>>();
    attn_kernel<<<BS, 256>>>(attn_out);
    fc_mma_kernel<<<dim3(4, 768), 256, GEMM_SMEM>>>(fc_b, outp);
    ln_kernel<<<NROWS, 128>>>(outp, ln_g, ln_b);
}

// round 14
// speedup vs baseline: 2.8549x; 1.6581x over previous
#include <cuda_runtime.h>
#include <cuda_fp16.h>
#include <cstdint>

// ---------------- problem constants ----------------
#define BS     16384
#define MSEG   6
#define DM     512
#define NH     8
#define DIN    6144
#define NROWS  (BS*MSEG)            // 98304
#define QKV_ELEMS (NROWS*DM)        // 50331648
#define INV_TEMP 0.125f
#define LN_EPS 1e-6f
#define WPACK  9437184              // 512*6144*3

// ---------------- scratch ----------------
__device__ float g_Q[QKV_ELEMS];
__device__ float g_K[QKV_ELEMS];
__device__ float g_V[QKV_ELEMS];
__device__ __half g_A[(size_t)BS*DIN];
__device__ __half g_W[WPACK];
__device__ __half g_FW[DM*DM];
__device__ __half g_AO[QKV_ELEMS];

// combo c = s*3 + w  (w: 0=q, 1=k, 2=v)
__constant__ int c_cK[18]   = {2048,2048,2048,1024,1024,1024,512,512,512,
                               1536,1536,1536,768,768,768,256,256,256};
__constant__ int c_cOff[18] = {0,0,0,2048,2048,2048,3072,3072,3072,
                               3584,3584,3584,5120,5120,5120,5888,5888,5888};
__constant__ int c_cW[18]   = {0,1048576,2097152,3145728,3670016,4194304,
                               4718592,4980736,5242880,5505024,6291456,7077888,
                               7864320,8257536,8650752,9043968,9175040,9306112};

struct WPtrs { const float* w[18]; };

// ---------------- helpers ----------------
__device__ __forceinline__ uint32_t smem_u32(const void* p) {
    uint32_t a;
    asm("{ .reg .u64 t; cvta.to.shared.u64 t, %1; cvt.u32.u64 %0, t; }" : "=r"(a) : "l"(p));
    return a;
}
__device__ __forceinline__ void cpa16(uint32_t s, const void* g) {
    asm volatile("cp.async.cg.shared.global [%0], [%1], 16;" :: "r"(s), "l"(g));
}
__device__ __forceinline__ void cpa_commit() { asm volatile("cp.async.commit_group;" ::: "memory"); }
__device__ __forceinline__ void cpa_wait1()  { asm volatile("cp.async.wait_group 1;" ::: "memory"); }

__device__ __forceinline__ void mma16816(float* c, const uint32_t* a, const uint32_t* b) {
    asm volatile(
        "mma.sync.aligned.m16n8k16.row.col.f32.f16.f16.f32 "
        "{%0,%1,%2,%3}, {%4,%5,%6,%7}, {%8,%9}, {%0,%1,%2,%3};"
        : "+f"(c[0]), "+f"(c[1]), "+f"(c[2]), "+f"(c[3])
        : "r"(a[0]), "r"(a[1]), "r"(a[2]), "r"(a[3]), "r"(b[0]), "r"(b[1]));
}
__device__ __forceinline__ void ldm_x4(uint32_t* r, uint32_t addr) {
    asm volatile("ldmatrix.sync.aligned.m8n8.x4.shared.b16 {%0,%1,%2,%3}, [%4];"
        : "=r"(r[0]), "=r"(r[1]), "=r"(r[2]), "=r"(r[3]) : "r"(addr));
}

// ---------------- conversion kernels ----------------
__global__ void __launch_bounds__(256) conv_input_kernel(const float* __restrict__ inp) {
    size_t i = (size_t)blockIdx.x * 256 + threadIdx.x;   // float4 index
    float4 x = ((const float4*)inp)[i];
    __half2 a = __floats2half2_rn(x.x, x.y);
    __half2 b = __floats2half2_rn(x.z, x.w);
    *(__half2*)(g_A + i*4)     = a;
    *(__half2*)(g_A + i*4 + 2) = b;
}

__global__ void __launch_bounds__(256) conv_w_kernel(WPtrs P) {
    int c = blockIdx.y;
    int n4 = (512 * c_cK[c]) >> 2;
    int i = blockIdx.x * 256 + threadIdx.x;
    if (i >= n4) return;
    float4 x = ((const float4*)P.w[c])[i];
    size_t base = (size_t)c_cW[c] + (size_t)i * 4;
    *(__half2*)(g_W + base)     = __floats2half2_rn(x.x, x.y);
    *(__half2*)(g_W + base + 2) = __floats2half2_rn(x.z, x.w);
}

__global__ void __launch_bounds__(256) conv_fcw_kernel(const float* __restrict__ fcw) {
    int i = blockIdx.x * 256 + threadIdx.x;   // 65536 float4s
    float4 x = ((const float4*)fcw)[i];
    *(__half2*)(g_FW + i*4)     = __floats2half2_rn(x.x, x.y);
    *(__half2*)(g_FW + i*4 + 2) = __floats2half2_rn(x.z, x.w);
}

// ---------------- mma.sync GEMM configuration ----------------
// CTA tile 128x128, BK=64 fp16, 1-term, 3-stage ring, 2 CTAs/SM, one barrier/iter.
// smem buffer: 128 rows x 128B, SW128 swizzle: 16B chunk c at c ^ (r & 7).
#define BUFB   16384              // bytes per buffer (128*128)
#define STAGE_BYTES (2*BUFB)      // 32768  [A|B]
#define GEMM_SMEM (3*STAGE_BYTES) // 98304

// one stage: 1024 chunks per buffer, 256 threads -> 4 per thread per buffer
__device__ __forceinline__ void load_stage_g(
    uint32_t sbase, int tid,
    const char* A, size_t strA, const char* B, size_t strB, size_t kb)
{
#pragma unroll
    for (int j = 0; j < 4; j++) {
        int q = tid + j * 256;
        int r = q >> 3, cc = q & 7;
        uint32_t so = (uint32_t)(r * 128 + ((cc ^ (r & 7)) << 4));
        cpa16(sbase + so,        A + (size_t)r * strA + kb + cc * 16);
        cpa16(sbase + BUFB + so, B + (size_t)r * strB + kb + cc * 16);
    }
    cpa_commit();
}

// per-lane ldmatrix layout: rowbyte = row*128, key = row&7, chunk0 = lane-group half
struct LdmOff { uint32_t arb, akey, ach0, brb, bkey, bch0; };
__device__ __forceinline__ LdmOff ldm_offsets(int wm, int wn, int lane)
{
    LdmOff o;
    int g = lane >> 3, r8 = lane & 7;
    int arow = wm * 32 + r8 + (g & 1) * 8;
    o.arb = (uint32_t)(arow * 128); o.akey = (uint32_t)(arow & 7); o.ach0 = (uint32_t)(g >> 1);
    int brow = wn * 64 + r8 + (g >> 1) * 8;
    o.brb = (uint32_t)(brow * 128); o.bkey = (uint32_t)(brow & 7); o.bch0 = (uint32_t)(g & 1);
    return o;
}

// compute one BK=64 stage: 24 ldmatrix + 64 HMMA per warp
__device__ __forceinline__ void compute_stage(
    uint32_t sstage, const LdmOff& o, float acc[2][8][4])
{
    const uint32_t A_ = sstage, B_ = sstage + BUFB;

#pragma unroll
    for (int k16 = 0; k16 < 4; k16++) {
        uint32_t ach = ((o.ach0 + 2*k16) ^ o.akey) << 4;
        uint32_t bch = ((o.bch0 + 2*k16) ^ o.bkey) << 4;
        uint32_t ah[2][4];
#pragma unroll
        for (int mt = 0; mt < 2; mt++)
            ldm_x4(ah[mt], A_ + o.arb + ach + mt * 2048);   // 16 rows * 128B
#pragma unroll
        for (int p = 0; p < 4; p++) {
            uint32_t bb[4];
            ldm_x4(bb, B_ + o.brb + bch + p * 2048);
#pragma unroll
            for (int mt = 0; mt < 2; mt++) {
                mma16816(acc[mt][2*p],   ah[mt], bb);
                mma16816(acc[mt][2*p+1], ah[mt], bb + 2);
            }
        }
    }
}

// 3-stage ring mainloop, one barrier per iteration
__device__ __forceinline__ void gemm_mainloop(
    uint32_t sb, int tid, int nc,
    const char* A, size_t strA, const char* B, size_t strB,
    const LdmOff& o, float acc[2][8][4])
{
    load_stage_g(sb,               tid, A, strA, B, strB, 0);
    load_stage_g(sb + STAGE_BYTES, tid, A, strA, B, strB, 128);

    uint32_t stg = 0;
    for (int i = 0; i < nc; i++) {
        cpa_wait1();
        __syncthreads();
        if (i + 2 < nc) {
            uint32_t nstg = stg + 2; if (nstg >= 3) nstg -= 3;
            load_stage_g(sb + nstg * STAGE_BYTES, tid,
                         A, strA, B, strB, (size_t)(i+2) * 128);
        } else {
            cpa_commit();
        }
        compute_stage(sb + stg * STAGE_BYTES, o, acc);
        if (++stg == 3) stg = 0;
    }
    __syncthreads();
}

// ---------------- QKV GEMM ----------------
// grid (4 ntiles, 128 mtiles, 18 combos), 256 threads.
__global__ void __launch_bounds__(256, 2)
qkv_mma_kernel()
{
    extern __shared__ char smem[];
    const uint32_t sb = smem_u32(smem);
    const int tid = threadIdx.x, wid = tid >> 5, lane = tid & 31;
    const int wm = wid & 3, wn = wid >> 2;
    const int n0 = blockIdx.x * 128;
    const int m0 = blockIdx.y * 128;
    const int c  = blockIdx.z;
    const int Kdim = c_cK[c];
    const int seg  = c_cOff[c];
    const int s = c / 3, w = c % 3;
    const int nc = Kdim >> 6;

    const char* A = (const char*)(g_A + (size_t)m0 * DIN + seg);
    const char* B = (const char*)(g_W + (size_t)c_cW[c] + (size_t)n0 * Kdim);
    const size_t strA = (size_t)DIN * 2, strB = (size_t)Kdim * 2;

    LdmOff o = ldm_offsets(wm, wn, lane);

    float acc[2][8][4];
#pragma unroll
    for (int i = 0; i < 2; i++)
#pragma unroll
        for (int j = 0; j < 8; j++)
#pragma unroll
            for (int k = 0; k < 4; k++) acc[i][j][k] = 0.0f;

    gemm_mainloop(sb, tid, nc, A, strA, B, strB, o, acc);

    // epilogue: acc -> smem (128 x 132 fp32) -> coalesced global
    float* tb = (float*)smem;
    {
        const int l4 = lane >> 2, lm = lane & 3;
#pragma unroll
        for (int mt = 0; mt < 2; mt++)
#pragma unroll
            for (int nt = 0; nt < 8; nt++) {
                int R = wm*32 + mt*16 + l4;
                int C = wn*64 + nt*8 + lm*2;
                tb[R*132 + C]       = acc[mt][nt][0];
                tb[R*132 + C + 1]   = acc[mt][nt][1];
                tb[(R+8)*132 + C]   = acc[mt][nt][2];
                tb[(R+8)*132 + C+1] = acc[mt][nt][3];
            }
    }
    __syncthreads();
    float* Cb = (w == 0) ? g_Q : (w == 1) ? g_K : g_V;
#pragma unroll
    for (int it = 0; it < 16; it++) {
        int v = tid + it * 256;
        int rr = v >> 5, c4 = (v & 31) * 4;
        float4 ov = make_float4(tb[rr*132 + c4], tb[rr*132 + c4 + 1],
                                tb[rr*132 + c4 + 2], tb[rr*132 + c4 + 3]);
        *(float4*)(Cb + ((size_t)(m0 + rr) * MSEG + s) * DM + n0 + c4) = ov;
    }
}

// ---------------- FC GEMM + bias + residual ----------------
// grid (4 ntiles, 768 mtiles), 256 threads. C = AO(98304x512) @ fcw^T
__global__ void __launch_bounds__(256, 2)
fc_mma_kernel(const float* __restrict__ fcb, float* __restrict__ outp)
{
    extern __shared__ char smem[];
    const uint32_t sb = smem_u32(smem);
    const int tid = threadIdx.x, wid = tid >> 5, lane = tid & 31;
    const int wm = wid & 3, wn = wid >> 2;
    const int n0 = blockIdx.x * 128;
    const int m0 = blockIdx.y * 128;
    const int nc = 8;                        // K = 512

    const char* A = (const char*)(g_AO + (size_t)m0 * DM);
    const char* B = (const char*)(g_FW + (size_t)n0 * DM);
    const size_t strA = (size_t)DM * 2, strB = (size_t)DM * 2;

    LdmOff o = ldm_offsets(wm, wn, lane);

    float acc[2][8][4];
#pragma unroll
    for (int i = 0; i < 2; i++)
#pragma unroll
        for (int j = 0; j < 8; j++)
#pragma unroll
            for (int k = 0; k < 4; k++) acc[i][j][k] = 0.0f;

    gemm_mainloop(sb, tid, nc, A, strA, B, strB, o, acc);

    float* tb = (float*)smem;
    {
        const int l4 = lane >> 2, lm = lane & 3;
#pragma unroll
        for (int mt = 0; mt < 2; mt++)
#pragma unroll
            for (int nt = 0; nt < 8; nt++) {
                int R = wm*32 + mt*16 + l4;
                int C = wn*64 + nt*8 + lm*2;
                tb[R*132 + C]       = acc[mt][nt][0];
                tb[R*132 + C + 1]   = acc[mt][nt][1];
                tb[(R+8)*132 + C]   = acc[mt][nt][2];
                tb[(R+8)*132 + C+1] = acc[mt][nt][3];
            }
    }
    __syncthreads();
#pragma unroll
    for (int it = 0; it < 16; it++) {
        int v = tid + it * 256;
        int rr = v >> 5, c4 = (v & 31) * 4;
        int m = m0 + rr, n = n0 + c4;
        float4 bb = *(const float4*)(fcb + n);
        float4 vv = *(const float4*)(g_V + (size_t)m * DM + n);
        float4 ov;
        ov.x = tb[rr*132 + c4]     + bb.x + vv.x;
        ov.y = tb[rr*132 + c4 + 1] + bb.y + vv.y;
        ov.z = tb[rr*132 + c4 + 2] + bb.z + vv.z;
        ov.w = tb[rr*132 + c4 + 3] + bb.w + vv.w;
        *(float4*)(outp + (size_t)m * DM + n) = ov;
    }
}

// ---------------- fused attention ----------------
// attn/|global min| then row-L2-normalize: the scale cancels (v*s/||v*s|| = v/||v||,
// s>0), so no cross-batch pass is needed.
__global__ void __launch_bounds__(256)
attn_kernel(float* __restrict__ attn_out)
{
    const int b    = blockIdx.x;
    const int tid  = threadIdx.x;
    const int h    = tid >> 5;
    const int lane = tid & 31;

    __shared__ float at[NH*36];

    const float* Qb = g_Q + (size_t)b * (MSEG*DM) + h * 64 + lane;
    const float* Kb = g_K + (size_t)b * (MSEG*DM) + h * 64 + lane;

    float q0[6], q1[6], k0v[6], k1v[6];
#pragma unroll
    for (int t = 0; t < 6; t++) {
        q0[t]  = Qb[t*DM];  q1[t]  = Qb[t*DM + 32];
        k0v[t] = Kb[t*DM];  k1v[t] = Kb[t*DM + 32];
    }

#pragma unroll
    for (int tq = 0; tq < 6; tq++) {
#pragma unroll
        for (int tk = 0; tk < 6; tk++) {
            float p = q0[tq]*k0v[tk] + q1[tq]*k1v[tk];
#pragma unroll
            for (int o = 16; o > 0; o >>= 1)
                p += __shfl_xor_sync(0xffffffffu, p, o);
            if (lane == 0) at[h*36 + tq*6 + tk] = p * INV_TEMP;
        }
    }
    __syncthreads();

    if (tid < 48) {
        int hh = tid / 6, tq = tid % 6;
        float* lp = &at[hh*36 + tq*6];
        float v[6]; float ss = 0.0f;
#pragma unroll
        for (int k = 0; k < 6; k++) { v[k] = lp[k]; ss += v[k]*v[k]; }
        float inorm = 1.0f / fmaxf(sqrtf(ss), 1e-30f);
        float mx = -3.4e38f;
#pragma unroll
        for (int k = 0; k < 6; k++) { v[k] *= inorm; mx = fmaxf(mx, v[k]); }
        float es = 0.0f; float e[6];
#pragma unroll
        for (int k = 0; k < 6; k++) { e[k] = expf(v[k] - mx); es += e[k]; }
        float r = 1.0f / es;
        float* ao = attn_out + ((size_t)b * NH + hh) * 36 + tq * 6;
#pragma unroll
        for (int k = 0; k < 6; k++) {
            float a = e[k] * r;
            lp[k] = a;
            ao[k] = a;
        }
    }
    __syncthreads();

    // AO[b,t,f] = sum_k attn[h,t,k] * V[b,k,f],  f = h*64+d ; fp16 out
    const float* Vb = g_V + (size_t)b * (MSEG*DM);
    size_t base = (size_t)b * (MSEG*DM);
    for (int idx = tid; idx < MSEG*DM; idx += 256) {
        int t = idx >> 9;
        int f = idx & 511;
        int hh = f >> 6;
        const float* ar = &at[hh*36 + t*6];
        float sv = 0.0f;
#pragma unroll
        for (int k = 0; k < 6; k++) sv += ar[k] * Vb[k*DM + f];
        g_AO[base + idx] = __float2half_rn(sv);
    }
}

// ---------------- LayerNorm ----------------
__global__ void __launch_bounds__(128)
ln_kernel(float* __restrict__ outp, const float* __restrict__ g,
          const float* __restrict__ be)
{
    const int row = blockIdx.x;
    float* p = outp + (size_t)row * DM;
    const int tid = threadIdx.x;

    float4 x = *(const float4*)(p + tid * 4);
    float s  = x.x + x.y + x.z + x.w;
    float sq = x.x*x.x + x.y*x.y + x.z*x.z + x.w*x.w;

#pragma unroll
    for (int o = 16; o > 0; o >>= 1) {
        s  += __shfl_xor_sync(0xffffffffu, s,  o);
        sq += __shfl_xor_sync(0xffffffffu, sq, o);
    }
    __shared__ float ws[4], wq[4];
    int w = tid >> 5, lane = tid & 31;
    if (lane == 0) { ws[w] = s; wq[w] = sq; }
    __syncthreads();
    s  = ws[0] + ws[1] + ws[2] + ws[3];
    sq = wq[0] + wq[1] + wq[2] + wq[3];

    float mu  = s * (1.0f / DM);
    float var = sq * (1.0f / DM) - mu * mu;
    float rstd = rsqrtf(var + LN_EPS);

    int c = tid * 4;
    float4 gg = *(const float4*)(g + c);
    float4 bb = *(const float4*)(be + c);
    float4 o;
    o.x = (x.x - mu) * rstd * gg.x + bb.x;
    o.y = (x.y - mu) * rstd * gg.y + bb.y;
    o.z = (x.z - mu) * rstd * gg.z + bb.z;
    o.w = (x.w - mu) * rstd * gg.w + bb.w;
    *(float4*)(p + c) = o;
}

// ---------------- launch ----------------
extern "C" void kernel_launch(void* const* d_in, const int* in_sizes, int n_in,
                              void* d_out, int out_size)
{
    const float* inp = (const float*)d_in[0];
    WPtrs P;
    for (int i = 0; i < 18; i++) P.w[i] = (const float*)d_in[1 + i];
    const float* fc_w = (const float*)d_in[19];
    const float* fc_b = (const float*)d_in[20];
    const float* ln_g = (const float*)d_in[21];
    const float* ln_b = (const float*)d_in[22];

    float* outp     = (float*)d_out;
    float* attn_out = outp + (size_t)NROWS * DM;

    cudaFuncSetAttribute(qkv_mma_kernel, cudaFuncAttributeMaxDynamicSharedMemorySize, GEMM_SMEM);
    cudaFuncSetAttribute(fc_mma_kernel,  cudaFuncAttributeMaxDynamicSharedMemorySize, GEMM_SMEM);

    conv_input_kernel<<<(BS*(size_t)DIN/4 + 255)/256, 256>>>(inp);
    conv_w_kernel<<<dim3(1024, 18), 256>>>(P);
    conv_fcw_kernel<<<256, 256>>>(fc_w);
    qkv_mma_kernel<<<dim3(4, 128, 18), 256, GEMM_SMEM>>>();
    attn_kernel<<<BS, 256>>>(attn_out);
    fc_mma_kernel<<<dim3(4, 768), 256, GEMM_SMEM>>>(fc_b, outp);
    ln_kernel<<<NROWS, 128>>>(outp, ln_g, ln_b);
}

// round 15
// speedup vs baseline: 3.1165x; 1.0916x over previous
#include <cuda_runtime.h>
#include <cuda_fp16.h>
#include <cstdint>

// ---------------- problem constants ----------------
#define BS     16384
#define MSEG   6
#define DM     512
#define NH     8
#define DIN    6144
#define NROWS  (BS*MSEG)            // 98304
#define QKV_ELEMS (NROWS*DM)        // 50331648
#define INV_TEMP 0.125f
#define LN_EPS 1e-6f
#define WPACK  9437184              // 512*6144*3

// ---------------- scratch ----------------
__device__ __half g_Q[QKV_ELEMS];
__device__ __half g_K[QKV_ELEMS];
__device__ __half g_V[QKV_ELEMS];
__device__ __half g_A[(size_t)BS*DIN];     // input fp16; reused as FC fp16 output scratch
__device__ __half g_W[WPACK];
__device__ __half g_FW[DM*DM];
__device__ __half g_AO[QKV_ELEMS];

// combo c = s*3 + w  (w: 0=q, 1=k, 2=v)
__constant__ int c_cK[18]   = {2048,2048,2048,1024,1024,1024,512,512,512,
                               1536,1536,1536,768,768,768,256,256,256};
__constant__ int c_cOff[18] = {0,0,0,2048,2048,2048,3072,3072,3072,
                               3584,3584,3584,5120,5120,5120,5888,5888,5888};
__constant__ int c_cW[18]   = {0,1048576,2097152,3145728,3670016,4194304,
                               4718592,4980736,5242880,5505024,6291456,7077888,
                               7864320,8257536,8650752,9043968,9175040,9306112};

struct WPtrs { const float* w[18]; };

// ---------------- helpers ----------------
__device__ __forceinline__ uint32_t smem_u32(const void* p) {
    uint32_t a;
    asm("{ .reg .u64 t; cvta.to.shared.u64 t, %1; cvt.u32.u64 %0, t; }" : "=r"(a) : "l"(p));
    return a;
}
__device__ __forceinline__ void cpa16(uint32_t s, const void* g) {
    asm volatile("cp.async.cg.shared.global [%0], [%1], 16;" :: "r"(s), "l"(g));
}
__device__ __forceinline__ void cpa_commit() { asm volatile("cp.async.commit_group;" ::: "memory"); }
__device__ __forceinline__ void cpa_wait1()  { asm volatile("cp.async.wait_group 1;" ::: "memory"); }

__device__ __forceinline__ void mma16816(float* c, const uint32_t* a, const uint32_t* b) {
    asm volatile(
        "mma.sync.aligned.m16n8k16.row.col.f32.f16.f16.f32 "
        "{%0,%1,%2,%3}, {%4,%5,%6,%7}, {%8,%9}, {%0,%1,%2,%3};"
        : "+f"(c[0]), "+f"(c[1]), "+f"(c[2]), "+f"(c[3])
        : "r"(a[0]), "r"(a[1]), "r"(a[2]), "r"(a[3]), "r"(b[0]), "r"(b[1]));
}
__device__ __forceinline__ void ldm_x4(uint32_t* r, uint32_t addr) {
    asm volatile("ldmatrix.sync.aligned.m8n8.x4.shared.b16 {%0,%1,%2,%3}, [%4];"
        : "=r"(r[0]), "=r"(r[1]), "=r"(r[2]), "=r"(r[3]) : "r"(addr));
}

// ---------------- conversion kernels ----------------
__global__ void __launch_bounds__(256) conv_input_kernel(const float* __restrict__ inp) {
    size_t i = (size_t)blockIdx.x * 256 + threadIdx.x;   // float4 index
    float4 x = ((const float4*)inp)[i];
    *(__half2*)(g_A + i*4)     = __floats2half2_rn(x.x, x.y);
    *(__half2*)(g_A + i*4 + 2) = __floats2half2_rn(x.z, x.w);
}

__global__ void __launch_bounds__(256) conv_w_kernel(WPtrs P) {
    int c = blockIdx.y;
    int n4 = (512 * c_cK[c]) >> 2;
    int i = blockIdx.x * 256 + threadIdx.x;
    if (i >= n4) return;
    float4 x = ((const float4*)P.w[c])[i];
    size_t base = (size_t)c_cW[c] + (size_t)i * 4;
    *(__half2*)(g_W + base)     = __floats2half2_rn(x.x, x.y);
    *(__half2*)(g_W + base + 2) = __floats2half2_rn(x.z, x.w);
}

__global__ void __launch_bounds__(256) conv_fcw_kernel(const float* __restrict__ fcw) {
    int i = blockIdx.x * 256 + threadIdx.x;   // 65536 float4s
    float4 x = ((const float4*)fcw)[i];
    *(__half2*)(g_FW + i*4)     = __floats2half2_rn(x.x, x.y);
    *(__half2*)(g_FW + i*4 + 2) = __floats2half2_rn(x.z, x.w);
}

// ---------------- mma.sync GEMM configuration ----------------
// CTA tile 128x128, BK=64 fp16, 1-term, 3-stage ring, 2 CTAs/SM, one barrier/iter.
// smem buffer: 128 rows x 128B, SW128 swizzle: 16B chunk c at c ^ (r & 7).
#define BUFB   16384              // bytes per buffer (128*128)
#define STAGE_BYTES (2*BUFB)      // 32768  [A|B]
#define GEMM_SMEM (3*STAGE_BYTES) // 98304

__device__ __forceinline__ void load_stage_g(
    uint32_t sbase, int tid,
    const char* A, size_t strA, const char* B, size_t strB, size_t kb)
{
#pragma unroll
    for (int j = 0; j < 4; j++) {
        int q = tid + j * 256;
        int r = q >> 3, cc = q & 7;
        uint32_t so = (uint32_t)(r * 128 + ((cc ^ (r & 7)) << 4));
        cpa16(sbase + so,        A + (size_t)r * strA + kb + cc * 16);
        cpa16(sbase + BUFB + so, B + (size_t)r * strB + kb + cc * 16);
    }
    cpa_commit();
}

struct LdmOff { uint32_t arb, akey, ach0, brb, bkey, bch0; };
__device__ __forceinline__ LdmOff ldm_offsets(int wm, int wn, int lane)
{
    LdmOff o;
    int g = lane >> 3, r8 = lane & 7;
    int arow = wm * 32 + r8 + (g & 1) * 8;
    o.arb = (uint32_t)(arow * 128); o.akey = (uint32_t)(arow & 7); o.ach0 = (uint32_t)(g >> 1);
    int brow = wn * 64 + r8 + (g >> 1) * 8;
    o.brb = (uint32_t)(brow * 128); o.bkey = (uint32_t)(brow & 7); o.bch0 = (uint32_t)(g & 1);
    return o;
}

// compute one BK=64 stage: 24 ldmatrix + 64 HMMA per warp
__device__ __forceinline__ void compute_stage(
    uint32_t sstage, const LdmOff& o, float acc[2][8][4])
{
    const uint32_t A_ = sstage, B_ = sstage + BUFB;

#pragma unroll
    for (int k16 = 0; k16 < 4; k16++) {
        uint32_t ach = ((o.ach0 + 2*k16) ^ o.akey) << 4;
        uint32_t bch = ((o.bch0 + 2*k16) ^ o.bkey) << 4;
        uint32_t ah[2][4];
#pragma unroll
        for (int mt = 0; mt < 2; mt++)
            ldm_x4(ah[mt], A_ + o.arb + ach + mt * 2048);   // 16 rows * 128B
#pragma unroll
        for (int p = 0; p < 4; p++) {
            uint32_t bb[4];
            ldm_x4(bb, B_ + o.brb + bch + p * 2048);
#pragma unroll
            for (int mt = 0; mt < 2; mt++) {
                mma16816(acc[mt][2*p],   ah[mt], bb);
                mma16816(acc[mt][2*p+1], ah[mt], bb + 2);
            }
        }
    }
}

// 3-stage ring mainloop, one barrier per iteration
__device__ __forceinline__ void gemm_mainloop(
    uint32_t sb, int tid, int nc,
    const char* A, size_t strA, const char* B, size_t strB,
    const LdmOff& o, float acc[2][8][4])
{
    load_stage_g(sb,               tid, A, strA, B, strB, 0);
    load_stage_g(sb + STAGE_BYTES, tid, A, strA, B, strB, 128);

    uint32_t stg = 0;
    for (int i = 0; i < nc; i++) {
        cpa_wait1();
        __syncthreads();
        if (i + 2 < nc) {
            uint32_t nstg = stg + 2; if (nstg >= 3) nstg -= 3;
            load_stage_g(sb + nstg * STAGE_BYTES, tid,
                         A, strA, B, strB, (size_t)(i+2) * 128);
        } else {
            cpa_commit();
        }
        compute_stage(sb + stg * STAGE_BYTES, o, acc);
        if (++stg == 3) stg = 0;
    }
    __syncthreads();
}

// write acc tile to smem as fp16 (pitch 136 halves -> conflict-free), then global
// returns via tb; caller does the coalesced stores
#define TPITCH 136

__device__ __forceinline__ void acc_to_smem_h(
    __half* tb, int wm, int wn, int lane, float acc[2][8][4])
{
    const int l4 = lane >> 2, lm = lane & 3;
#pragma unroll
    for (int mt = 0; mt < 2; mt++)
#pragma unroll
        for (int nt = 0; nt < 8; nt++) {
            int R = wm*32 + mt*16 + l4;
            int C = wn*64 + nt*8 + lm*2;
            *(__half2*)(tb + R*TPITCH + C)     = __floats2half2_rn(acc[mt][nt][0], acc[mt][nt][1]);
            *(__half2*)(tb + (R+8)*TPITCH + C) = __floats2half2_rn(acc[mt][nt][2], acc[mt][nt][3]);
        }
}

// ---------------- QKV GEMM ----------------
// grid (4 ntiles, 128 mtiles, 18 combos), 256 threads. Output fp16.
__global__ void __launch_bounds__(256, 2)
qkv_mma_kernel()
{
    extern __shared__ char smem[];
    const uint32_t sb = smem_u32(smem);
    const int tid = threadIdx.x, wid = tid >> 5, lane = tid & 31;
    const int wm = wid & 3, wn = wid >> 2;
    const int n0 = blockIdx.x * 128;
    const int m0 = blockIdx.y * 128;
    const int c  = blockIdx.z;
    const int Kdim = c_cK[c];
    const int seg  = c_cOff[c];
    const int s = c / 3, w = c % 3;
    const int nc = Kdim >> 6;

    const char* A = (const char*)(g_A + (size_t)m0 * DIN + seg);
    const char* B = (const char*)(g_W + (size_t)c_cW[c] + (size_t)n0 * Kdim);
    const size_t strA = (size_t)DIN * 2, strB = (size_t)Kdim * 2;

    LdmOff o = ldm_offsets(wm, wn, lane);

    float acc[2][8][4];
#pragma unroll
    for (int i = 0; i < 2; i++)
#pragma unroll
        for (int j = 0; j < 8; j++)
#pragma unroll
            for (int k = 0; k < 4; k++) acc[i][j][k] = 0.0f;

    gemm_mainloop(sb, tid, nc, A, strA, B, strB, o, acc);

    // epilogue: acc -> fp16 smem -> coalesced fp16 global
    __half* tb = (__half*)smem;
    acc_to_smem_h(tb, wm, wn, lane, acc);
    __syncthreads();
    __half* Cb = (w == 0) ? g_Q : (w == 1) ? g_K : g_V;
#pragma unroll
    for (int it = 0; it < 8; it++) {
        int v = tid + it * 256;                // 2048 chunks of 8 halves
        int rr = v >> 4, c8 = (v & 15) * 8;
        uint4 d = *(const uint4*)(tb + rr*TPITCH + c8);
        *(uint4*)(Cb + ((size_t)(m0 + rr) * MSEG + s) * DM + n0 + c8) = d;
    }
}

// ---------------- FC GEMM + bias + residual (fp16 out to g_A scratch) ----------------
// grid (4 ntiles, 768 mtiles), 256 threads. C = AO(98304x512) @ fcw^T
__global__ void __launch_bounds__(256, 2)
fc_mma_kernel(const float* __restrict__ fcb)
{
    extern __shared__ char smem[];
    const uint32_t sb = smem_u32(smem);
    const int tid = threadIdx.x, wid = tid >> 5, lane = tid & 31;
    const int wm = wid & 3, wn = wid >> 2;
    const int n0 = blockIdx.x * 128;
    const int m0 = blockIdx.y * 128;
    const int nc = 8;                        // K = 512

    const char* A = (const char*)(g_AO + (size_t)m0 * DM);
    const char* B = (const char*)(g_FW + (size_t)n0 * DM);
    const size_t strA = (size_t)DM * 2, strB = (size_t)DM * 2;

    LdmOff o = ldm_offsets(wm, wn, lane);

    float acc[2][8][4];
#pragma unroll
    for (int i = 0; i < 2; i++)
#pragma unroll
        for (int j = 0; j < 8; j++)
#pragma unroll
            for (int k = 0; k < 4; k++) acc[i][j][k] = 0.0f;

    gemm_mainloop(sb, tid, nc, A, strA, B, strB, o, acc);

    __half* tb = (__half*)smem;
    acc_to_smem_h(tb, wm, wn, lane, acc);
    __syncthreads();
    // add bias + V residual, write fp16 scratch (g_A, dead after QKV)
#pragma unroll
    for (int it = 0; it < 8; it++) {
        int v = tid + it * 256;
        int rr = v >> 4, c8 = (v & 15) * 8;
        int m = m0 + rr, n = n0 + c8;
        const __half* tr = tb + rr*TPITCH + c8;
        const __half* vr = g_V + (size_t)m * DM + n;
        const float*  br = fcb + n;
        __half out[8];
#pragma unroll
        for (int j = 0; j < 8; j++)
            out[j] = __float2half_rn(__half2float(tr[j]) + br[j] + __half2float(vr[j]));
        *(uint4*)(g_A + (size_t)m * DM + n) = *(const uint4*)out;
    }
}

// ---------------- fused attention ----------------
// attn/|global min| then row-L2-normalize: the scale cancels (v*s/||v*s|| = v/||v||,
// s>0), so no cross-batch pass is needed. Q/K/V fp16 in, AO fp16 out.
__global__ void __launch_bounds__(256)
attn_kernel(float* __restrict__ attn_out)
{
    const int b    = blockIdx.x;
    const int tid  = threadIdx.x;
    const int h    = tid >> 5;
    const int lane = tid & 31;

    __shared__ float at[NH*36];

    const __half* Qb = g_Q + (size_t)b * (MSEG*DM) + h * 64 + lane;
    const __half* Kb = g_K + (size_t)b * (MSEG*DM) + h * 64 + lane;

    float q0[6], q1[6], k0v[6], k1v[6];
#pragma unroll
    for (int t = 0; t < 6; t++) {
        q0[t]  = __half2float(Qb[t*DM]);  q1[t]  = __half2float(Qb[t*DM + 32]);
        k0v[t] = __half2float(Kb[t*DM]);  k1v[t] = __half2float(Kb[t*DM + 32]);
    }

#pragma unroll
    for (int tq = 0; tq < 6; tq++) {
#pragma unroll
        for (int tk = 0; tk < 6; tk++) {
            float p = q0[tq]*k0v[tk] + q1[tq]*k1v[tk];
#pragma unroll
            for (int o = 16; o > 0; o >>= 1)
                p += __shfl_xor_sync(0xffffffffu, p, o);
            if (lane == 0) at[h*36 + tq*6 + tk] = p * INV_TEMP;
        }
    }
    __syncthreads();

    if (tid < 48) {
        int hh = tid / 6, tq = tid % 6;
        float* lp = &at[hh*36 + tq*6];
        float v[6]; float ss = 0.0f;
#pragma unroll
        for (int k = 0; k < 6; k++) { v[k] = lp[k]; ss += v[k]*v[k]; }
        float inorm = 1.0f / fmaxf(sqrtf(ss), 1e-30f);
        float mx = -3.4e38f;
#pragma unroll
        for (int k = 0; k < 6; k++) { v[k] *= inorm; mx = fmaxf(mx, v[k]); }
        float es = 0.0f; float e[6];
#pragma unroll
        for (int k = 0; k < 6; k++) { e[k] = expf(v[k] - mx); es += e[k]; }
        float r = 1.0f / es;
        float* ao = attn_out + ((size_t)b * NH + hh) * 36 + tq * 6;
#pragma unroll
        for (int k = 0; k < 6; k++) {
            float a = e[k] * r;
            lp[k] = a;
            ao[k] = a;
        }
    }
    __syncthreads();

    // AO[b,t,f] = sum_k attn[h,t,k] * V[b,k,f],  f = h*64+d ; fp16 out
    const __half* Vb = g_V + (size_t)b * (MSEG*DM);
    size_t base = (size_t)b * (MSEG*DM);
    for (int idx = tid; idx < MSEG*DM; idx += 256) {
        int t = idx >> 9;
        int f = idx & 511;
        int hh = f >> 6;
        const float* ar = &at[hh*36 + t*6];
        float sv = 0.0f;
#pragma unroll
        for (int k = 0; k < 6; k++) sv += ar[k] * __half2float(Vb[k*DM + f]);
        g_AO[base + idx] = __float2half_rn(sv);
    }
}

// ---------------- LayerNorm (fp16 in from g_A scratch, fp32 out) ----------------
__global__ void __launch_bounds__(128)
ln_kernel(float* __restrict__ outp, const float* __restrict__ g,
          const float* __restrict__ be)
{
    const int row = blockIdx.x;
    const __half* p = g_A + (size_t)row * DM;
    const int tid = threadIdx.x;

    __half2 a = *(const __half2*)(p + tid * 4);
    __half2 b = *(const __half2*)(p + tid * 4 + 2);
    float2 f0 = __half22float2(a), f1 = __half22float2(b);
    float x0 = f0.x, x1 = f0.y, x2 = f1.x, x3 = f1.y;
    float s  = x0 + x1 + x2 + x3;
    float sq = x0*x0 + x1*x1 + x2*x2 + x3*x3;

#pragma unroll
    for (int o = 16; o > 0; o >>= 1) {
        s  += __shfl_xor_sync(0xffffffffu, s,  o);
        sq += __shfl_xor_sync(0xffffffffu, sq, o);
    }
    __shared__ float ws[4], wq[4];
    int w = tid >> 5, lane = tid & 31;
    if (lane == 0) { ws[w] = s; wq[w] = sq; }
    __syncthreads();
    s  = ws[0] + ws[1] + ws[2] + ws[3];
    sq = wq[0] + wq[1] + wq[2] + wq[3];

    float mu  = s * (1.0f / DM);
    float var = sq * (1.0f / DM) - mu * mu;
    float rstd = rsqrtf(var + LN_EPS);

    int c = tid * 4;
    float4 gg = *(const float4*)(g + c);
    float4 bb = *(const float4*)(be + c);
    float4 o;
    o.x = (x0 - mu) * rstd * gg.x + bb.x;
    o.y = (x1 - mu) * rstd * gg.y + bb.y;
    o.z = (x2 - mu) * rstd * gg.z + bb.z;
    o.w = (x3 - mu) * rstd * gg.w + bb.w;
    *(float4*)(outp + (size_t)row * DM + c) = o;
}

// ---------------- launch ----------------
extern "C" void kernel_launch(void* const* d_in, const int* in_sizes, int n_in,
                              void* d_out, int out_size)
{
    const float* inp = (const float*)d_in[0];
    WPtrs P;
    for (int i = 0; i < 18; i++) P.w[i] = (const float*)d_in[1 + i];
    const float* fc_w = (const float*)d_in[19];
    const float* fc_b = (const float*)d_in[20];
    const float* ln_g = (const float*)d_in[21];
    const float* ln_b = (const float*)d_in[22];

    float* outp     = (float*)d_out;
    float* attn_out = outp + (size_t)NROWS * DM;

    cudaFuncSetAttribute(qkv_mma_kernel, cudaFuncAttributeMaxDynamicSharedMemorySize, GEMM_SMEM);
    cudaFuncSetAttribute(fc_mma_kernel,  cudaFuncAttributeMaxDynamicSharedMemorySize, GEMM_SMEM);

    conv_input_kernel<<<(BS*(size_t)DIN/4 + 255)/256, 256>>>(inp);
    conv_w_kernel<<<dim3(1024, 18), 256>>>(P);
    conv_fcw_kernel<<<256, 256>>>(fc_w);
    qkv_mma_kernel<<<dim3(4, 128, 18), 256, GEMM_SMEM>>>();
    attn_kernel<<<BS, 256>>>(attn_out);
    fc_mma_kernel<<<dim3(4, 768), 256, GEMM_SMEM>>>(fc_b);
    ln_kernel<<<NROWS, 128>>>(outp, ln_g, ln_b);
}

// round 16
// speedup vs baseline: 3.2400x; 1.0396x over previous
#include <cuda_runtime.h>
#include <cuda_fp16.h>
#include <cstdint>

// ---------------- problem constants ----------------
#define BS     16384
#define MSEG   6
#define DM     512
#define NH     8
#define DIN    6144
#define NROWS  (BS*MSEG)            // 98304
#define QKV_ELEMS (NROWS*DM)        // 50331648
#define INV_TEMP 0.125f
#define LN_EPS 1e-6f
#define WPACK  9437184              // 512*6144*3

// ---------------- scratch ----------------
__device__ __half g_Q[QKV_ELEMS];
__device__ __half g_K[QKV_ELEMS];
__device__ __half g_V[QKV_ELEMS];
__device__ __half g_A[(size_t)BS*DIN];     // input fp16; reused as FC fp16 output scratch
__device__ __half g_W[WPACK];
__device__ __half g_FW[DM*DM];
__device__ __half g_AO[QKV_ELEMS];

// per segment s
__constant__ int c_sK[6]   = {2048,1024,512,1536,768,256};
__constant__ int c_sOff[6] = {0,2048,3072,3584,5120,5888};
// weight pack offset for combo c = s*3 + w
__constant__ int c_cW[18]  = {0,1048576,2097152,3145728,3670016,4194304,
                              4718592,4980736,5242880,5505024,6291456,7077888,
                              7864320,8257536,8650752,9043968,9175040,9306112};

struct WPtrs { const float* w[18]; };
__constant__ int c_cK[18]   = {2048,2048,2048,1024,1024,1024,512,512,512,
                               1536,1536,1536,768,768,768,256,256,256};

// ---------------- helpers ----------------
__device__ __forceinline__ uint32_t smem_u32(const void* p) {
    uint32_t a;
    asm("{ .reg .u64 t; cvta.to.shared.u64 t, %1; cvt.u32.u64 %0, t; }" : "=r"(a) : "l"(p));
    return a;
}
__device__ __forceinline__ void cpa16(uint32_t s, const void* g) {
    asm volatile("cp.async.cg.shared.global [%0], [%1], 16;" :: "r"(s), "l"(g));
}
__device__ __forceinline__ void cpa_commit() { asm volatile("cp.async.commit_group;" ::: "memory"); }
__device__ __forceinline__ void cpa_wait1()  { asm volatile("cp.async.wait_group 1;" ::: "memory"); }

__device__ __forceinline__ void mma16816(float* c, const uint32_t* a, const uint32_t* b) {
    asm volatile(
        "mma.sync.aligned.m16n8k16.row.col.f32.f16.f16.f32 "
        "{%0,%1,%2,%3}, {%4,%5,%6,%7}, {%8,%9}, {%0,%1,%2,%3};"
        : "+f"(c[0]), "+f"(c[1]), "+f"(c[2]), "+f"(c[3])
        : "r"(a[0]), "r"(a[1]), "r"(a[2]), "r"(a[3]), "r"(b[0]), "r"(b[1]));
}
__device__ __forceinline__ void ldm_x4(uint32_t* r, uint32_t addr) {
    asm volatile("ldmatrix.sync.aligned.m8n8.x4.shared.b16 {%0,%1,%2,%3}, [%4];"
        : "=r"(r[0]), "=r"(r[1]), "=r"(r[2]), "=r"(r[3]) : "r"(addr));
}

// ---------------- conversion kernels ----------------
__global__ void __launch_bounds__(256) conv_input_kernel(const float* __restrict__ inp) {
    size_t i = (size_t)blockIdx.x * 256 + threadIdx.x;   // float4 index
    float4 x = ((const float4*)inp)[i];
    *(__half2*)(g_A + i*4)     = __floats2half2_rn(x.x, x.y);
    *(__half2*)(g_A + i*4 + 2) = __floats2half2_rn(x.z, x.w);
}

__global__ void __launch_bounds__(256) conv_w_kernel(WPtrs P) {
    int c = blockIdx.y;
    int n4 = (512 * c_cK[c]) >> 2;
    int i = blockIdx.x * 256 + threadIdx.x;
    if (i >= n4) return;
    float4 x = ((const float4*)P.w[c])[i];
    size_t base = (size_t)c_cW[c] + (size_t)i * 4;
    *(__half2*)(g_W + base)     = __floats2half2_rn(x.x, x.y);
    *(__half2*)(g_W + base + 2) = __floats2half2_rn(x.z, x.w);
}

__global__ void __launch_bounds__(256) conv_fcw_kernel(const float* __restrict__ fcw) {
    int i = blockIdx.x * 256 + threadIdx.x;   // 65536 float4s
    float4 x = ((const float4*)fcw)[i];
    *(__half2*)(g_FW + i*4)     = __floats2half2_rn(x.x, x.y);
    *(__half2*)(g_FW + i*4 + 2) = __floats2half2_rn(x.z, x.w);
}

// ---------------- mma.sync GEMM configuration ----------------
// CTA tile 128x128, BK=64 fp16, 1-term, 3-stage ring, 2 CTAs/SM, one barrier/iter.
// smem buffer: 128 rows x 128B, SW128 swizzle: 16B chunk c at c ^ (r & 7).
#define BUFB   16384              // bytes per buffer (128*128)
#define STAGE_BYTES (2*BUFB)      // 32768  [A|B]
#define GEMM_SMEM (3*STAGE_BYTES) // 98304

__device__ __forceinline__ void load_stage_g(
    uint32_t sbase, int tid,
    const char* A, size_t strA, const char* B, size_t strB, size_t kb)
{
#pragma unroll
    for (int j = 0; j < 4; j++) {
        int q = tid + j * 256;
        int r = q >> 3, cc = q & 7;
        uint32_t so = (uint32_t)(r * 128 + ((cc ^ (r & 7)) << 4));
        cpa16(sbase + so,        A + (size_t)r * strA + kb + cc * 16);
        cpa16(sbase + BUFB + so, B + (size_t)r * strB + kb + cc * 16);
    }
    cpa_commit();
}

struct LdmOff { uint32_t arb, akey, ach0, brb, bkey, bch0; };
__device__ __forceinline__ LdmOff ldm_offsets(int wm, int wn, int lane)
{
    LdmOff o;
    int g = lane >> 3, r8 = lane & 7;
    int arow = wm * 32 + r8 + (g & 1) * 8;
    o.arb = (uint32_t)(arow * 128); o.akey = (uint32_t)(arow & 7); o.ach0 = (uint32_t)(g >> 1);
    int brow = wn * 64 + r8 + (g >> 1) * 8;
    o.brb = (uint32_t)(brow * 128); o.bkey = (uint32_t)(brow & 7); o.bch0 = (uint32_t)(g & 1);
    return o;
}

// compute one BK=64 stage: 24 ldmatrix + 64 HMMA per warp
__device__ __forceinline__ void compute_stage(
    uint32_t sstage, const LdmOff& o, float acc[2][8][4])
{
    const uint32_t A_ = sstage, B_ = sstage + BUFB;

#pragma unroll
    for (int k16 = 0; k16 < 4; k16++) {
        uint32_t ach = ((o.ach0 + 2*k16) ^ o.akey) << 4;
        uint32_t bch = ((o.bch0 + 2*k16) ^ o.bkey) << 4;
        uint32_t ah[2][4];
#pragma unroll
        for (int mt = 0; mt < 2; mt++)
            ldm_x4(ah[mt], A_ + o.arb + ach + mt * 2048);   // 16 rows * 128B
#pragma unroll
        for (int p = 0; p < 4; p++) {
            uint32_t bb[4];
            ldm_x4(bb, B_ + o.brb + bch + p * 2048);
#pragma unroll
            for (int mt = 0; mt < 2; mt++) {
                mma16816(acc[mt][2*p],   ah[mt], bb);
                mma16816(acc[mt][2*p+1], ah[mt], bb + 2);
            }
        }
    }
}

// 3-stage ring mainloop, one barrier per iteration
__device__ __forceinline__ void gemm_mainloop(
    uint32_t sb, int tid, int nc,
    const char* A, size_t strA, const char* B, size_t strB,
    const LdmOff& o, float acc[2][8][4])
{
    load_stage_g(sb,               tid, A, strA, B, strB, 0);
    load_stage_g(sb + STAGE_BYTES, tid, A, strA, B, strB, 128);

    uint32_t stg = 0;
    for (int i = 0; i < nc; i++) {
        cpa_wait1();
        __syncthreads();
        if (i + 2 < nc) {
            uint32_t nstg = stg + 2; if (nstg >= 3) nstg -= 3;
            load_stage_g(sb + nstg * STAGE_BYTES, tid,
                         A, strA, B, strB, (size_t)(i+2) * 128);
        } else {
            cpa_commit();
        }
        compute_stage(sb + stg * STAGE_BYTES, o, acc);
        if (++stg == 3) stg = 0;
    }
    __syncthreads();
}

// write acc tile to smem as fp16 (pitch 136 halves -> conflict-free)
#define TPITCH 136

__device__ __forceinline__ void acc_to_smem_h(
    __half* tb, int wm, int wn, int lane, float acc[2][8][4])
{
    const int l4 = lane >> 2, lm = lane & 3;
#pragma unroll
    for (int mt = 0; mt < 2; mt++)
#pragma unroll
        for (int nt = 0; nt < 8; nt++) {
            int R = wm*32 + mt*16 + l4;
            int C = wn*64 + nt*8 + lm*2;
            *(__half2*)(tb + R*TPITCH + C)     = __floats2half2_rn(acc[mt][nt][0], acc[mt][nt][1]);
            *(__half2*)(tb + (R+8)*TPITCH + C) = __floats2half2_rn(acc[mt][nt][2], acc[mt][nt][3]);
        }
}

// ---------------- QKV GEMM ----------------
// grid (12 ntiles = q|k|v x 4, 128 mtiles, 6 segments), 256 threads. Output fp16.
// q/k/v fused in blockIdx.x so the 12 CTAs sharing an A-tile are co-resident (L2 reuse).
__global__ void __launch_bounds__(256, 2)
qkv_mma_kernel()
{
    extern __shared__ char smem[];
    const uint32_t sb = smem_u32(smem);
    const int tid = threadIdx.x, wid = tid >> 5, lane = tid & 31;
    const int wm = wid & 3, wn = wid >> 2;
    const int nG = blockIdx.x * 128;        // 0..1535
    const int m0 = blockIdx.y * 128;
    const int s  = blockIdx.z;
    const int w  = nG >> 9;                 // 0=q 1=k 2=v
    const int n0 = nG & 511;
    const int Kdim = c_sK[s];
    const int seg  = c_sOff[s];
    const int nc = Kdim >> 6;

    const char* A = (const char*)(g_A + (size_t)m0 * DIN + seg);
    const char* B = (const char*)(g_W + (size_t)c_cW[s*3 + w] + (size_t)n0 * Kdim);
    const size_t strA = (size_t)DIN * 2, strB = (size_t)Kdim * 2;

    LdmOff o = ldm_offsets(wm, wn, lane);

    float acc[2][8][4];
#pragma unroll
    for (int i = 0; i < 2; i++)
#pragma unroll
        for (int j = 0; j < 8; j++)
#pragma unroll
            for (int k = 0; k < 4; k++) acc[i][j][k] = 0.0f;

    gemm_mainloop(sb, tid, nc, A, strA, B, strB, o, acc);

    // epilogue: acc -> fp16 smem -> coalesced fp16 global
    __half* tb = (__half*)smem;
    acc_to_smem_h(tb, wm, wn, lane, acc);
    __syncthreads();
    __half* Cb = (w == 0) ? g_Q : (w == 1) ? g_K : g_V;
#pragma unroll
    for (int it = 0; it < 8; it++) {
        int v = tid + it * 256;                // 2048 chunks of 8 halves
        int rr = v >> 4, c8 = (v & 15) * 8;
        uint4 d = *(const uint4*)(tb + rr*TPITCH + c8);
        *(uint4*)(Cb + ((size_t)(m0 + rr) * MSEG + s) * DM + n0 + c8) = d;
    }
}

// ---------------- FC GEMM + bias + residual (fp16 out to g_A scratch) ----------------
// grid (4 ntiles, 768 mtiles), 256 threads. C = AO(98304x512) @ fcw^T
__global__ void __launch_bounds__(256, 2)
fc_mma_kernel(const float* __restrict__ fcb)
{
    extern __shared__ char smem[];
    const uint32_t sb = smem_u32(smem);
    const int tid = threadIdx.x, wid = tid >> 5, lane = tid & 31;
    const int wm = wid & 3, wn = wid >> 2;
    const int n0 = blockIdx.x * 128;
    const int m0 = blockIdx.y * 128;
    const int nc = 8;                        // K = 512

    const char* A = (const char*)(g_AO + (size_t)m0 * DM);
    const char* B = (const char*)(g_FW + (size_t)n0 * DM);
    const size_t strA = (size_t)DM * 2, strB = (size_t)DM * 2;

    LdmOff o = ldm_offsets(wm, wn, lane);

    float acc[2][8][4];
#pragma unroll
    for (int i = 0; i < 2; i++)
#pragma unroll
        for (int j = 0; j < 8; j++)
#pragma unroll
            for (int k = 0; k < 4; k++) acc[i][j][k] = 0.0f;

    gemm_mainloop(sb, tid, nc, A, strA, B, strB, o, acc);

    __half* tb = (__half*)smem;
    acc_to_smem_h(tb, wm, wn, lane, acc);
    __syncthreads();
    // add bias + V residual, write fp16 scratch (g_A, dead after QKV)
#pragma unroll
    for (int it = 0; it < 8; it++) {
        int v = tid + it * 256;
        int rr = v >> 4, c8 = (v & 15) * 8;
        int m = m0 + rr, n = n0 + c8;
        const __half* tr = tb + rr*TPITCH + c8;
        const __half* vr = g_V + (size_t)m * DM + n;
        const float*  br = fcb + n;
        __half out[8];
#pragma unroll
        for (int j = 0; j < 8; j++)
            out[j] = __float2half_rn(__half2float(tr[j]) + br[j] + __half2float(vr[j]));
        *(uint4*)(g_A + (size_t)m * DM + n) = *(const uint4*)out;
    }
}

// ---------------- fused attention (half2 vectorized) ----------------
// attn/|global min| then row-L2-normalize: the scale cancels (v*s/||v*s|| = v/||v||,
// s>0), so no cross-batch pass is needed. Q/K/V fp16 in, AO fp16 out.
__global__ void __launch_bounds__(256)
attn_kernel(float* __restrict__ attn_out)
{
    const int b    = blockIdx.x;
    const int tid  = threadIdx.x;
    const int h    = tid >> 5;
    const int lane = tid & 31;

    __shared__ float at[NH*36];

    // lane covers dims 2*lane, 2*lane+1 of this head -> full 128B line per warp load
    const __half2* Qb = (const __half2*)(g_Q + (size_t)b * (MSEG*DM) + h * 64) + lane;
    const __half2* Kb = (const __half2*)(g_K + (size_t)b * (MSEG*DM) + h * 64) + lane;

    float2 q[6], k[6];
#pragma unroll
    for (int t = 0; t < 6; t++) {
        q[t] = __half22float2(Qb[t*(DM/2)]);
        k[t] = __half22float2(Kb[t*(DM/2)]);
    }

#pragma unroll
    for (int tq = 0; tq < 6; tq++) {
#pragma unroll
        for (int tk = 0; tk < 6; tk++) {
            float p = q[tq].x*k[tk].x + q[tq].y*k[tk].y;
#pragma unroll
            for (int o = 16; o > 0; o >>= 1)
                p += __shfl_xor_sync(0xffffffffu, p, o);
            if (lane == 0) at[h*36 + tq*6 + tk] = p * INV_TEMP;
        }
    }
    __syncthreads();

    if (tid < 48) {
        int hh = tid / 6, tq = tid % 6;
        float* lp = &at[hh*36 + tq*6];
        float v[6]; float ss = 0.0f;
#pragma unroll
        for (int kk = 0; kk < 6; kk++) { v[kk] = lp[kk]; ss += v[kk]*v[kk]; }
        float inorm = 1.0f / fmaxf(sqrtf(ss), 1e-30f);
        float mx = -3.4e38f;
#pragma unroll
        for (int kk = 0; kk < 6; kk++) { v[kk] *= inorm; mx = fmaxf(mx, v[kk]); }
        float es = 0.0f; float e[6];
#pragma unroll
        for (int kk = 0; kk < 6; kk++) { e[kk] = expf(v[kk] - mx); es += e[kk]; }
        float r = 1.0f / es;
        float* ao = attn_out + ((size_t)b * NH + hh) * 36 + tq * 6;
#pragma unroll
        for (int kk = 0; kk < 6; kk++) {
            float a = e[kk] * r;
            lp[kk] = a;
            ao[kk] = a;
        }
    }
    __syncthreads();

    // AO[b,t,f] = sum_k attn[h,t,k] * V[b,k,f] ; half2 over f
    const __half2* Vb = (const __half2*)(g_V + (size_t)b * (MSEG*DM));
    __half2* AOb = (__half2*)(g_AO + (size_t)b * (MSEG*DM));
    for (int idx = tid; idx < MSEG*(DM/2); idx += 256) {
        int t  = idx >> 8;            // / 256
        int f2 = idx & 255;
        int hh = f2 >> 5;             // (2*f2) >> 6
        const float* ar = &at[hh*36 + t*6];
        float sx = 0.0f, sy = 0.0f;
#pragma unroll
        for (int kk = 0; kk < 6; kk++) {
            float2 vv = __half22float2(Vb[kk*(DM/2) + f2]);
            sx += ar[kk] * vv.x;
            sy += ar[kk] * vv.y;
        }
        AOb[idx] = __floats2half2_rn(sx, sy);
    }
}

// ---------------- LayerNorm (fp16 in from g_A scratch, fp32 out) ----------------
__global__ void __launch_bounds__(128)
ln_kernel(float* __restrict__ outp, const float* __restrict__ g,
          const float* __restrict__ be)
{
    const int row = blockIdx.x;
    const __half* p = g_A + (size_t)row * DM;
    const int tid = threadIdx.x;

    __half2 a = *(const __half2*)(p + tid * 4);
    __half2 b = *(const __half2*)(p + tid * 4 + 2);
    float2 f0 = __half22float2(a), f1 = __half22float2(b);
    float x0 = f0.x, x1 = f0.y, x2 = f1.x, x3 = f1.y;
    float s  = x0 + x1 + x2 + x3;
    float sq = x0*x0 + x1*x1 + x2*x2 + x3*x3;

#pragma unroll
    for (int o = 16; o > 0; o >>= 1) {
        s  += __shfl_xor_sync(0xffffffffu, s,  o);
        sq += __shfl_xor_sync(0xffffffffu, sq, o);
    }
    __shared__ float ws[4], wq[4];
    int w = tid >> 5, lane = tid & 31;
    if (lane == 0) { ws[w] = s; wq[w] = sq; }
    __syncthreads();
    s  = ws[0] + ws[1] + ws[2] + ws[3];
    sq = wq[0] + wq[1] + wq[2] + wq[3];

    float mu  = s * (1.0f / DM);
    float var = sq * (1.0f / DM) - mu * mu;
    float rstd = rsqrtf(var + LN_EPS);

    int c = tid * 4;
    float4 gg = *(const float4*)(g + c);
    float4 bb = *(const float4*)(be + c);
    float4 o;
    o.x = (x0 - mu) * rstd * gg.x + bb.x;
    o.y = (x1 - mu) * rstd * gg.y + bb.y;
    o.z = (x2 - mu) * rstd * gg.z + bb.z;
    o.w = (x3 - mu) * rstd * gg.w + bb.w;
    *(float4*)(outp + (size_t)row * DM + c) = o;
}

// ---------------- launch ----------------
extern "C" void kernel_launch(void* const* d_in, const int* in_sizes, int n_in,
                              void* d_out, int out_size)
{
    const float* inp = (const float*)d_in[0];
    WPtrs P;
    for (int i = 0; i < 18; i++) P.w[i] = (const float*)d_in[1 + i];
    const float* fc_w = (const float*)d_in[19];
    const float* fc_b = (const float*)d_in[20];
    const float* ln_g = (const float*)d_in[21];
    const float* ln_b = (const float*)d_in[22];

    float* outp     = (float*)d_out;
    float* attn_out = outp + (size_t)NROWS * DM;

    cudaFuncSetAttribute(qkv_mma_kernel, cudaFuncAttributeMaxDynamicSharedMemorySize, GEMM_SMEM);
    cudaFuncSetAttribute(fc_mma_kernel,  cudaFuncAttributeMaxDynamicSharedMemorySize, GEMM_SMEM);

    conv_input_kernel<<<(BS*(size_t)DIN/4 + 255)/256, 256>>>(inp);
    conv_w_kernel<<<dim3(1024, 18), 256>>>(P);
    conv_fcw_kernel<<<256, 256>>>(fc_w);
    qkv_mma_kernel<<<dim3(12, 128, 6), 256, GEMM_SMEM>>>();
    attn_kernel<<<BS, 256>>>(attn_out);
    fc_mma_kernel<<<dim3(4, 768), 256, GEMM_SMEM>>>(fc_b);
    ln_kernel<<<NROWS, 128>>>(outp, ln_g, ln_b);
}